// round 15
// baseline (speedup 1.0000x reference)
#include <cuda_runtime.h>
#include <cuda_bf16.h>
#include <cstdint>

#define N_HOSTN 50000
#define N_FLOWN 200000
#define NEDGE   1000000
#define DIM     128
#define D_OUT   32

// ---------------- device scratch (static: no allocations allowed) ----------
__device__ int   g_deg[N_FLOWN + 1];
__device__ int   g_rowptr_f[N_FLOWN + 1];
__device__ int   g_rowptr_h[N_HOSTN + 1];
__device__ int   g_col_f[NEDGE];
__device__ int   g_col_h[NEDGE];
__device__ int   g_partials[256];
__device__ int   g_partials_h[256];
__device__ int   g_deg_h[N_HOSTN + 1];
__device__ float g_zero[DIM];            // zero bias (static zero-init)
// activations as bf16 hi/lo planes
__device__ __nv_bfloat16 g_xfh[(size_t)N_FLOWN * DIM], g_xfl[(size_t)N_FLOWN * DIM];
__device__ __nv_bfloat16 g_xhh[(size_t)N_HOSTN * DIM], g_xhl[(size_t)N_HOSTN * DIM];
__device__ __nv_bfloat16 g_faH[(size_t)N_FLOWN * DIM], g_faL[(size_t)N_FLOWN * DIM];
__device__ __nv_bfloat16 g_haH[(size_t)N_HOSTN * DIM], g_haL[(size_t)N_HOSTN * DIM];
__device__ __nv_bfloat16 g_mhH[(size_t)N_HOSTN * DIM], g_mhL[(size_t)N_HOSTN * DIM];
// pre-multiplied host features y = h @ Wl (per flow layer), fp32
__device__ float g_y0[(size_t)N_HOSTN * DIM];
__device__ float g_y2[(size_t)N_HOSTN * DIM];
// aggregated fp32 addends for flow GEMMs
__device__ float g_D1[(size_t)N_FLOWN * DIM];
__device__ float g_D2[(size_t)N_FLOWN * DIM];
// weights: host dual [128n][256k]; flow WrT/WlT [2][128n][128k]; Wout [32n][128k]
__device__ __nv_bfloat16 g_dualh[128 * 256], g_duall[128 * 256];
__device__ __nv_bfloat16 g_wrTh[2 * 128 * 128], g_wrTl[2 * 128 * 128];
__device__ __nv_bfloat16 g_wlTh[2 * 128 * 128], g_wlTl[2 * 128 * 128];
__device__ __nv_bfloat16 g_fhi[32 * 128], g_flo[32 * 128];

// ---------------- helpers ----------------------------------------------------
__device__ __forceinline__ uint32_t smem_u32(const void* p) {
    return (uint32_t)__cvta_generic_to_shared(p);
}

__device__ __forceinline__ void ldsm4(uint32_t* r, uint32_t addr) {
    asm volatile("ldmatrix.sync.aligned.m8n8.x4.shared.b16 {%0,%1,%2,%3}, [%4];"
                 : "=r"(r[0]), "=r"(r[1]), "=r"(r[2]), "=r"(r[3]) : "r"(addr));
}

__device__ __forceinline__ void mma_bf16(float* c, const uint32_t* a, const uint32_t* b) {
    asm volatile(
        "mma.sync.aligned.m16n8k16.row.col.f32.bf16.bf16.f32 "
        "{%0,%1,%2,%3}, {%4,%5,%6,%7}, {%8,%9}, {%0,%1,%2,%3};"
        : "+f"(c[0]), "+f"(c[1]), "+f"(c[2]), "+f"(c[3])
        : "r"(a[0]), "r"(a[1]), "r"(a[2]), "r"(a[3]), "r"(b[0]), "r"(b[1]));
}

__device__ __forceinline__ uint32_t pack2(__nv_bfloat16 a, __nv_bfloat16 b) {
    uint32_t lo = (uint32_t)__bfloat16_as_ushort(a);
    uint32_t hi = (uint32_t)__bfloat16_as_ushort(b);
    return lo | (hi << 16);
}

__device__ __forceinline__ float2 bf2f(uint32_t u) {
    float2 r;
    r.x = __bfloat162float(__ushort_as_bfloat16((unsigned short)(u & 0xffff)));
    r.y = __bfloat162float(__ushort_as_bfloat16((unsigned short)(u >> 16)));
    return r;
}

__device__ __forceinline__ void cpa16(uint32_t dst, const void* src, int szbytes) {
    asm volatile("cp.async.cg.shared.global [%0], [%1], 16, %2;"
                 :: "r"(dst), "l"(src), "r"(szbytes));
}

// ---------------- small utility kernels ------------------------------------
__global__ void zero_kernel(int* p, int n) {
    int i = blockIdx.x * blockDim.x + threadIdx.x;
    if (i < n) p[i] = 0;
}

__global__ void hist_kernel(const int* __restrict__ dst, int* __restrict__ deg, int n) {
    for (int i = blockIdx.x * blockDim.x + threadIdx.x; i < n; i += gridDim.x * blockDim.x)
        atomicAdd(&deg[dst[i]], 1);
}

__global__ void scan_blocks(const int* __restrict__ in, int* __restrict__ out,
                            int* __restrict__ partials, int n) {
    __shared__ int sh[256];
    int t = threadIdx.x;
    int base = blockIdx.x * 1024 + t * 4;
    int v0 = (base + 0 < n) ? in[base + 0] : 0;
    int v1 = (base + 1 < n) ? in[base + 1] : 0;
    int v2 = (base + 2 < n) ? in[base + 2] : 0;
    int v3 = (base + 3 < n) ? in[base + 3] : 0;
    int s = v0 + v1 + v2 + v3;
    sh[t] = s;
    __syncthreads();
    for (int off = 1; off < 256; off <<= 1) {
        int y = (t >= off) ? sh[t - off] : 0;
        __syncthreads();
        sh[t] += y;
        __syncthreads();
    }
    int excl = sh[t] - s;
    if (t == 255) partials[blockIdx.x] = sh[255];
    int run = excl;
    if (base + 0 < n) out[base + 0] = run; run += v0;
    if (base + 1 < n) out[base + 1] = run; run += v1;
    if (base + 2 < n) out[base + 2] = run; run += v2;
    if (base + 3 < n) out[base + 3] = run;
}

__global__ void scan_partials(int* partials, int nb) {
    __shared__ int sh[256];
    int t = threadIdx.x;
    int v = (t < nb) ? partials[t] : 0;
    sh[t] = v;
    __syncthreads();
    for (int off = 1; off < 256; off <<= 1) {
        int y = (t >= off) ? sh[t - off] : 0;
        __syncthreads();
        sh[t] += y;
        __syncthreads();
    }
    if (t < nb) partials[t] = sh[t] - v;
}

__global__ void scan_add(int* __restrict__ out, const int* __restrict__ partials, int n) {
    for (int i = blockIdx.x * blockDim.x + threadIdx.x; i < n; i += gridDim.x * blockDim.x)
        out[i] += partials[i >> 10];
}

__global__ void fill_kernel(const int* __restrict__ src, const int* __restrict__ dst,
                            const int* __restrict__ rowptr, int* __restrict__ cursor,
                            int* __restrict__ col, int n) {
    for (int e = blockIdx.x * blockDim.x + threadIdx.x; e < n; e += gridDim.x * blockDim.x) {
        int d = dst[e];
        int p = rowptr[d] + atomicAdd(&cursor[d], 1);
        col[p] = src[e];
    }
}

// fp32 [N][128] -> bf16 hi/lo planes
__global__ void conv_hl(const float* __restrict__ x, __nv_bfloat16* __restrict__ hi,
                        __nv_bfloat16* __restrict__ lo, int nq) {
    int i = blockIdx.x * blockDim.x + threadIdx.x;
    if (i >= nq) return;
    float4 v = ((const float4*)x)[i];
    __nv_bfloat16 h0 = __float2bfloat16(v.x), h1 = __float2bfloat16(v.y);
    __nv_bfloat16 h2 = __float2bfloat16(v.z), h3 = __float2bfloat16(v.w);
    __nv_bfloat16 l0 = __float2bfloat16(v.x - __bfloat162float(h0));
    __nv_bfloat16 l1 = __float2bfloat16(v.y - __bfloat162float(h1));
    __nv_bfloat16 l2 = __float2bfloat16(v.z - __bfloat162float(h2));
    __nv_bfloat16 l3 = __float2bfloat16(v.w - __bfloat162float(h3));
    ((uint2*)hi)[i] = make_uint2(pack2(h0, h1), pack2(h2, h3));
    ((uint2*)lo)[i] = make_uint2(pack2(l0, l1), pack2(l2, l3));
}

// transposed bf16 hi/lo weight planes
__global__ void prep_weights(const float* __restrict__ Wl, const float* __restrict__ Wr,
                             const float* __restrict__ W_out,
                             __nv_bfloat16* __restrict__ dualh, __nv_bfloat16* __restrict__ duall,
                             __nv_bfloat16* __restrict__ wrTh, __nv_bfloat16* __restrict__ wrTl,
                             __nv_bfloat16* __restrict__ wlTh, __nv_bfloat16* __restrict__ wlTl,
                             __nv_bfloat16* __restrict__ fhi, __nv_bfloat16* __restrict__ flo) {
    int i = blockIdx.x * blockDim.x + threadIdx.x;
    if (i >= 102400) return;
    float v;
    __nv_bfloat16* dh;
    __nv_bfloat16* dl;
    int idx;
    if (i < 32768) {
        int n = i >> 8, k = i & 255;
        if (k < DIM) v = Wl[((size_t)1 * DIM + k) * DIM + n];
        else         v = Wr[((size_t)1 * DIM + (k - DIM)) * DIM + n];
        dh = dualh; dl = duall; idx = i;
    } else if (i < 65536) {
        int r = i - 32768;
        int g = r >> 14, rr = r & 16383;
        int n = rr >> 7, k = rr & 127;
        v = Wr[((size_t)(g * 2 + 0) * DIM + k) * DIM + n];
        dh = wrTh; dl = wrTl; idx = r;
    } else if (i < 98304) {
        int r = i - 65536;
        int g = r >> 14, rr = r & 16383;
        int n = rr >> 7, k = rr & 127;
        v = Wl[((size_t)(g * 2 + 0) * DIM + k) * DIM + n];
        dh = wlTh; dl = wlTl; idx = r;
    } else {
        int r = i - 98304;
        int n = r >> 7, k = r & 127;
        v = W_out[(size_t)k * D_OUT + n];
        dh = fhi; dl = flo; idx = r;
    }
    __nv_bfloat16 h = __float2bfloat16(v);
    dh[idx] = h;
    dl[idx] = __float2bfloat16(v - __bfloat162float(h));
}

// ---------------- mean aggregation, bf16-plane gather -> bf16 planes ---------
__global__ void aggregate_hl(const __nv_bfloat16* __restrict__ hi,
                             const __nv_bfloat16* __restrict__ lo,
                             const int* __restrict__ rowptr,
                             const int* __restrict__ col,
                             __nv_bfloat16* __restrict__ mh,
                             __nv_bfloat16* __restrict__ ml, int ndst) {
    int warp = (blockIdx.x * blockDim.x + threadIdx.x) >> 5;
    int lane = threadIdx.x & 31;
    if (warp >= ndst) return;
    int start = rowptr[warp];
    int end   = rowptr[warp + 1];
    const uint4* P = (const uint4*)((lane < 16) ? hi : lo);
    int fo = lane & 15;
    float a[8];
#pragma unroll
    for (int j = 0; j < 8; j++) a[j] = 0.f;
    int e = start;
    for (; e + 1 < end; e += 2) {
        int s0 = __ldg(&col[e]);
        int s1 = __ldg(&col[e + 1]);
        uint4 v0 = __ldg(&P[(size_t)s0 * 16 + fo]);
        uint4 v1 = __ldg(&P[(size_t)s1 * 16 + fo]);
        float2 p;
        p = bf2f(v0.x); a[0] += p.x; a[1] += p.y;
        p = bf2f(v0.y); a[2] += p.x; a[3] += p.y;
        p = bf2f(v0.z); a[4] += p.x; a[5] += p.y;
        p = bf2f(v0.w); a[6] += p.x; a[7] += p.y;
        p = bf2f(v1.x); a[0] += p.x; a[1] += p.y;
        p = bf2f(v1.y); a[2] += p.x; a[3] += p.y;
        p = bf2f(v1.z); a[4] += p.x; a[5] += p.y;
        p = bf2f(v1.w); a[6] += p.x; a[7] += p.y;
    }
    if (e < end) {
        int s0 = __ldg(&col[e]);
        uint4 v0 = __ldg(&P[(size_t)s0 * 16 + fo]);
        float2 p;
        p = bf2f(v0.x); a[0] += p.x; a[1] += p.y;
        p = bf2f(v0.y); a[2] += p.x; a[3] += p.y;
        p = bf2f(v0.z); a[4] += p.x; a[5] += p.y;
        p = bf2f(v0.w); a[6] += p.x; a[7] += p.y;
    }
#pragma unroll
    for (int j = 0; j < 8; j++) a[j] += __shfl_down_sync(0xffffffffu, a[j], 16);
    if (lane < 16) {
        int deg = end - start;
        float inv = 1.f / (float)(deg > 1 ? deg : 1);
        uint4 oh, ol;
        uint32_t* ph = (uint32_t*)&oh;
        uint32_t* pl = (uint32_t*)&ol;
#pragma unroll
        for (int j = 0; j < 4; j++) {
            float m0 = a[2 * j] * inv;
            float m1 = a[2 * j + 1] * inv;
            __nv_bfloat16 h0 = __float2bfloat16(m0);
            __nv_bfloat16 h1 = __float2bfloat16(m1);
            __nv_bfloat16 l0 = __float2bfloat16(m0 - __bfloat162float(h0));
            __nv_bfloat16 l1 = __float2bfloat16(m1 - __bfloat162float(h1));
            ph[j] = pack2(h0, h1);
            pl[j] = pack2(l0, l1);
        }
        ((uint4*)mh)[(size_t)warp * 16 + fo] = oh;
        ((uint4*)ml)[(size_t)warp * 16 + fo] = ol;
    }
}

// ---------------- mean aggregation, flat fp32 gather -> fp32 addend ----------
__global__ void aggregate_flat(const float* __restrict__ y,
                               const int* __restrict__ rowptr,
                               const int* __restrict__ col,
                               float* __restrict__ D, int ndst) {
    int warp = (blockIdx.x * blockDim.x + threadIdx.x) >> 5;
    int lane = threadIdx.x & 31;
    if (warp >= ndst) return;
    int start = rowptr[warp];
    int end   = rowptr[warp + 1];
    const float4* P = (const float4*)y;
    float a0 = 0.f, a1 = 0.f, a2 = 0.f, a3 = 0.f;
    int e = start;
    for (; e + 1 < end; e += 2) {
        int s0 = __ldg(&col[e]);
        int s1 = __ldg(&col[e + 1]);
        float4 v0 = __ldg(&P[(size_t)s0 * 32 + lane]);
        float4 v1 = __ldg(&P[(size_t)s1 * 32 + lane]);
        a0 += v0.x + v1.x; a1 += v0.y + v1.y;
        a2 += v0.z + v1.z; a3 += v0.w + v1.w;
    }
    if (e < end) {
        int s0 = __ldg(&col[e]);
        float4 v0 = __ldg(&P[(size_t)s0 * 32 + lane]);
        a0 += v0.x; a1 += v0.y; a2 += v0.z; a3 += v0.w;
    }
    int deg = end - start;
    float inv = 1.f / (float)(deg > 1 ? deg : 1);
    ((float4*)D)[(size_t)warp * 32 + lane] = make_float4(a0 * inv, a1 * inv,
                                                         a2 * inv, a3 * inv);
}

// ---------------- mma.sync bf16 GEMM, 3-pass hi/lo, cp.async 2-stage ---------
// AD: optional fp32 [M][128] addend before act. FUSE: second GEMM @ FW[32][128].
template <int BN, int WROWS, int KTOT, bool DUAL, bool ACT, bool WHL, bool FUSE>
__global__ __launch_bounds__(256) void mma_gemm(
    const __nv_bfloat16* __restrict__ Ah0, const __nv_bfloat16* __restrict__ Al0,
    const __nv_bfloat16* __restrict__ Ah1, const __nv_bfloat16* __restrict__ Al1,
    const __nv_bfloat16* __restrict__ Bh, const __nv_bfloat16* __restrict__ Bl,
    const float* __restrict__ bias0, const float* __restrict__ bias1,
    const float* __restrict__ AD,
    float* __restrict__ C, __nv_bfloat16* __restrict__ OutH,
    __nv_bfloat16* __restrict__ OutL,
    const __nv_bfloat16* __restrict__ FWh, const __nv_bfloat16* __restrict__ FWl,
    const float* __restrict__ bout, int M)
{
    constexpr int WCOLS  = 8 / WROWS;
    constexpr int WARP_M = 128 / WROWS;
    constexpr int WARP_N = BN / WCOLS;
    constexpr int TM = WARP_M / 16;
    constexpr int TN = WARP_N / 8;
    constexpr int AS = 40;
    constexpr int A_PLANE = 128 * AS * 2;
    constexpr int B_PLANE = BN * AS * 2;
    constexpr int STAGE = 2 * A_PLANE + 2 * B_PLANE;
    constexpr int NK = KTOT / 32;
    constexpr int PC = 68;

    extern __shared__ char dynsmem[];
    __shared__ float s_bias[BN];

    const int tid  = threadIdx.x;
    const int wid  = tid >> 5;
    const int lane = tid & 31;
    const int wrow = wid / WCOLS;
    const int wcol = wid % WCOLS;
    const int rowbase = blockIdx.x * 128;
    const uint32_t sb = smem_u32(dynsmem);

    if (tid < BN) s_bias[tid] = bias0[tid] + (bias1 ? bias1[tid] : 0.f);

    float acc[TM][TN][4];
#pragma unroll
    for (int i = 0; i < TM; i++)
#pragma unroll
        for (int j = 0; j < TN; j++)
#pragma unroll
            for (int q = 0; q < 4; q++) acc[i][j][q] = 0.f;

    uint32_t aoff[TM][2];
#pragma unroll
    for (int i = 0; i < TM; i++)
#pragma unroll
        for (int ks = 0; ks < 2; ks++) {
            int row = wrow * WARP_M + i * 16 + (lane & 15);
            int colk = ks * 16 + (lane >> 4) * 8;
            aoff[i][ks] = (uint32_t)(row * AS + colk) * 2;
        }
    uint32_t boff[TN / 2][2];
#pragma unroll
    for (int jj = 0; jj < TN / 2; jj++)
#pragma unroll
        for (int ks = 0; ks < 2; ks++) {
            int n = wcol * WARP_N + jj * 16 + (lane & 7) + ((lane >> 4) & 1) * 8;
            int k = ks * 16 + ((lane >> 3) & 1) * 8;
            boff[jj][ks] = (uint32_t)(n * AS + k) * 2;
        }

    auto load_stage = [&](int s, int k0) {
        uint32_t su = sb + (uint32_t)s * STAGE;
        const __nv_bfloat16* A_h = Ah0;
        const __nv_bfloat16* A_l = Al0;
        int ka = k0;
        if (DUAL && k0 >= DIM) { A_h = Ah1; A_l = Al1; ka = k0 - DIM; }
#pragma unroll
        for (int idx = tid; idx < 512; idx += 256) {
            int r = idx >> 2, q = idx & 3;
            int row = rowbase + r;
            int sz = (row < M) ? 16 : 0;
            int crow = row < M ? row : (M - 1);
            uint32_t d = su + (uint32_t)(r * AS + q * 8) * 2;
            cpa16(d, A_h + (size_t)crow * DIM + ka + q * 8, sz);
            cpa16(d + A_PLANE, A_l + (size_t)crow * DIM + ka + q * 8, sz);
        }
#pragma unroll
        for (int idx = tid; idx < BN * 4; idx += 256) {
            int n = idx >> 2, q = idx & 3;
            uint32_t d = su + 2 * A_PLANE + (uint32_t)(n * AS + q * 8) * 2;
            cpa16(d, Bh + (size_t)n * KTOT + k0 + q * 8, 16);
            cpa16(d + B_PLANE, Bl + (size_t)n * KTOT + k0 + q * 8, 16);
        }
        asm volatile("cp.async.commit_group;");
    };

    load_stage(0, 0);

    for (int c = 0; c < NK; c++) {
        if (c + 1 < NK) {
            load_stage((c + 1) & 1, (c + 1) * 32);
            asm volatile("cp.async.wait_group 1;");
        } else {
            asm volatile("cp.async.wait_group 0;");
        }
        __syncthreads();

        uint32_t su = sb + (uint32_t)(c & 1) * STAGE;
        const uint32_t uAh = su;
        const uint32_t uAl = su + A_PLANE;
        const uint32_t uBh = su + 2 * A_PLANE;
        const uint32_t uBl = uBh + B_PLANE;

#pragma unroll
        for (int ks = 0; ks < 2; ks++) {
            uint32_t ah[TM][4], al[TM][4];
#pragma unroll
            for (int i = 0; i < TM; i++) {
                ldsm4(ah[i], uAh + aoff[i][ks]);
                ldsm4(al[i], uAl + aoff[i][ks]);
            }
            uint32_t bh[TN][2], bl_[TN][2];
#pragma unroll
            for (int jj = 0; jj < TN / 2; jj++) {
                uint32_t r4[4];
                ldsm4(r4, uBh + boff[jj][ks]);
                bh[2 * jj][0] = r4[0]; bh[2 * jj][1] = r4[1];
                bh[2 * jj + 1][0] = r4[2]; bh[2 * jj + 1][1] = r4[3];
                ldsm4(r4, uBl + boff[jj][ks]);
                bl_[2 * jj][0] = r4[0]; bl_[2 * jj][1] = r4[1];
                bl_[2 * jj + 1][0] = r4[2]; bl_[2 * jj + 1][1] = r4[3];
            }
#pragma unroll
            for (int i = 0; i < TM; i++)
#pragma unroll
                for (int j = 0; j < TN; j++) {
                    mma_bf16(acc[i][j], ah[i], bh[j]);
                    mma_bf16(acc[i][j], ah[i], bl_[j]);
                    mma_bf16(acc[i][j], al[i], bh[j]);
                }
        }
        __syncthreads();
    }

    if (!FUSE) {
#pragma unroll
        for (int i = 0; i < TM; i++) {
#pragma unroll
            for (int j = 0; j < TN; j++) {
                int row0 = rowbase + wrow * WARP_M + i * 16 + (lane >> 2);
                int colb = wcol * WARP_N + j * 8 + (lane & 3) * 2;
                float b0 = s_bias[colb], b1 = s_bias[colb + 1];
#pragma unroll
                for (int h = 0; h < 2; h++) {
                    int row = row0 + h * 8;
                    if (row < M) {
                        float dx = 0.f, dy = 0.f;
                        if (AD) {
                            float2 dv = *(const float2*)&AD[(size_t)row * DIM + colb];
                            dx = dv.x; dy = dv.y;
                        }
                        float vx = acc[i][j][2 * h + 0] + b0 + dx;
                        float vy = acc[i][j][2 * h + 1] + b1 + dy;
                        if (ACT) {
                            vx = vx > 0.f ? vx : 0.01f * vx;
                            vy = vy > 0.f ? vy : 0.01f * vy;
                        }
                        if (WHL) {
                            __nv_bfloat16 hx = __float2bfloat16(vx);
                            __nv_bfloat16 hy = __float2bfloat16(vy);
                            __nv_bfloat16 lx = __float2bfloat16(vx - __bfloat162float(hx));
                            __nv_bfloat16 ly = __float2bfloat16(vy - __bfloat162float(hy));
                            *(uint32_t*)&OutH[(size_t)row * BN + colb] = pack2(hx, hy);
                            *(uint32_t*)&OutL[(size_t)row * BN + colb] = pack2(lx, ly);
                        } else {
                            *(float2*)&C[(size_t)row * BN + colb] = make_float2(vx, vy);
                        }
                    }
                }
            }
        }
    } else {
        // ---- fused output projection: act-tile (smem, bf16 hi/lo pairs) @ Wout
        uint32_t* sC_hi = (uint32_t*)dynsmem;          // [128][PC]
        uint32_t* sC_lo = sC_hi + 128 * PC;
        uint32_t* sW_hi = sC_lo + 128 * PC;            // [32][PC]
        uint32_t* sW_lo = sW_hi + 32 * PC;

        for (int idx = tid; idx < 32 * 64; idx += 256) {
            int n = idx >> 6, kp = idx & 63;
            sW_hi[n * PC + kp] = ((const uint32_t*)FWh)[n * 64 + kp];
            sW_lo[n * PC + kp] = ((const uint32_t*)FWl)[n * 64 + kp];
        }
#pragma unroll
        for (int i = 0; i < TM; i++) {
#pragma unroll
            for (int j = 0; j < TN; j++) {
                int lrow0 = wrow * WARP_M + i * 16 + (lane >> 2);
                int colb = wcol * WARP_N + j * 8 + (lane & 3) * 2;
                int pair = colb >> 1;
                float b0 = s_bias[colb], b1 = s_bias[colb + 1];
#pragma unroll
                for (int h = 0; h < 2; h++) {
                    int lrow = lrow0 + h * 8;
                    int grow = rowbase + lrow;
                    float dx = 0.f, dy = 0.f;
                    if (AD && grow < M) {
                        float2 dv = *(const float2*)&AD[(size_t)grow * DIM + colb];
                        dx = dv.x; dy = dv.y;
                    }
                    float vx = acc[i][j][2 * h + 0] + b0 + dx;
                    float vy = acc[i][j][2 * h + 1] + b1 + dy;
                    vx = vx > 0.f ? vx : 0.01f * vx;
                    vy = vy > 0.f ? vy : 0.01f * vy;
                    __nv_bfloat16 hx = __float2bfloat16(vx);
                    __nv_bfloat16 hy = __float2bfloat16(vy);
                    __nv_bfloat16 lx = __float2bfloat16(vx - __bfloat162float(hx));
                    __nv_bfloat16 ly = __float2bfloat16(vy - __bfloat162float(hy));
                    sC_hi[lrow * PC + pair] = pack2(hx, hy);
                    sC_lo[lrow * PC + pair] = pack2(lx, ly);
                }
            }
        }
        __syncthreads();

        const int g = lane >> 2, tig = lane & 3;
        const int w2row = wid * 16;
        float acc2[4][4];
#pragma unroll
        for (int j = 0; j < 4; j++)
#pragma unroll
            for (int q = 0; q < 4; q++) acc2[j][q] = 0.f;

#pragma unroll
        for (int ks = 0; ks < 8; ks++) {
            int ro  = (w2row + g) * PC + ks * 8 + tig;
            int ro8 = ro + 8 * PC;
            uint32_t ah[4] = {sC_hi[ro], sC_hi[ro8], sC_hi[ro + 4], sC_hi[ro8 + 4]};
            uint32_t al[4] = {sC_lo[ro], sC_lo[ro8], sC_lo[ro + 4], sC_lo[ro8 + 4]};
#pragma unroll
            for (int j = 0; j < 4; j++) {
                int bo = (j * 8 + g) * PC + ks * 8 + tig;
                uint32_t bh[2]  = {sW_hi[bo], sW_hi[bo + 4]};
                uint32_t bl2[2] = {sW_lo[bo], sW_lo[bo + 4]};
                mma_bf16(acc2[j], ah, bh);
                mma_bf16(acc2[j], ah, bl2);
                mma_bf16(acc2[j], al, bh);
            }
        }
#pragma unroll
        for (int j = 0; j < 4; j++) {
            int colo = j * 8 + tig * 2;
            float bo0 = bout[colo], bo1 = bout[colo + 1];
            int r0 = rowbase + w2row + g;
            if (r0 < M)
                *(float2*)&C[(size_t)r0 * D_OUT + colo] =
                    make_float2(acc2[j][0] + bo0, acc2[j][1] + bo1);
            int r1 = r0 + 8;
            if (r1 < M)
                *(float2*)&C[(size_t)r1 * D_OUT + colo] =
                    make_float2(acc2[j][2] + bo0, acc2[j][3] + bo1);
        }
    }
}

// ---------------- host side -------------------------------------------------
static void build_csr(const int* src, const int* dst, int ndst,
                      int* rowptr, int* col, int* deg, int* parts, cudaStream_t st) {
    int n1 = ndst + 1;
    zero_kernel<<<(n1 + 255) / 256, 256, 0, st>>>(deg, n1);
    hist_kernel<<<2048, 256, 0, st>>>(dst, deg, NEDGE);
    int nb = (n1 + 1023) / 1024;
    scan_blocks<<<nb, 256, 0, st>>>(deg, rowptr, parts, n1);
    scan_partials<<<1, 256, 0, st>>>(parts, nb);
    scan_add<<<nb, 256, 0, st>>>(rowptr, parts, n1);
    zero_kernel<<<(n1 + 255) / 256, 256, 0, st>>>(deg, n1);
    fill_kernel<<<2048, 256, 0, st>>>(src, dst, rowptr, deg, col, NEDGE);
}

extern "C" void kernel_launch(void* const* d_in, const int* in_sizes, int n_in,
                              void* d_out, int out_size) {
    (void)in_sizes; (void)n_in; (void)out_size;
    const float* x_host  = (const float*)d_in[0];
    const float* x_flow  = (const float*)d_in[1];
    const int*   ehf_src = (const int*)d_in[2];
    const int*   ehf_dst = (const int*)d_in[3];
    const int*   efh_src = (const int*)d_in[4];
    const int*   efh_dst = (const int*)d_in[5];
    const float* Wl      = (const float*)d_in[6];
    const float* bl      = (const float*)d_in[7];
    const float* Wr      = (const float*)d_in[8];
    const float* br      = (const float*)d_in[9];
    const float* W_out   = (const float*)d_in[10];
    const float* b_out   = (const float*)d_in[11];
    float* out = (float*)d_out;

    static bool inited = false;
    static cudaStream_t s1, s2, s3;
    static cudaEvent_t evFork, evPH, evConvF, evCsrF, evCsrH, evS1done;
    if (!inited) {
        cudaStreamCreateWithFlags(&s1, cudaStreamNonBlocking);
        cudaStreamCreateWithFlags(&s2, cudaStreamNonBlocking);
        cudaStreamCreateWithFlags(&s3, cudaStreamNonBlocking);
        cudaEventCreateWithFlags(&evFork,   cudaEventDisableTiming);
        cudaEventCreateWithFlags(&evPH,     cudaEventDisableTiming);
        cudaEventCreateWithFlags(&evConvF,  cudaEventDisableTiming);
        cudaEventCreateWithFlags(&evCsrF,   cudaEventDisableTiming);
        cudaEventCreateWithFlags(&evCsrH,   cudaEventDisableTiming);
        cudaEventCreateWithFlags(&evS1done, cudaEventDisableTiming);
        inited = true;
    }

    int *deg, *degh, *rpf, *rph, *colf, *colh, *parts, *partsh;
    float *zerob, *D1, *D2, *y0, *y2;
    __nv_bfloat16 *xfh, *xfl, *xhh, *xhl, *faH, *faL, *haH, *haL, *mhH, *mhL;
    __nv_bfloat16 *dualh, *duall, *wrTh, *wrTl, *wlTh, *wlTl, *fhi, *flo;
    cudaGetSymbolAddress((void**)&deg,    g_deg);
    cudaGetSymbolAddress((void**)&degh,   g_deg_h);
    cudaGetSymbolAddress((void**)&rpf,    g_rowptr_f);
    cudaGetSymbolAddress((void**)&rph,    g_rowptr_h);
    cudaGetSymbolAddress((void**)&colf,   g_col_f);
    cudaGetSymbolAddress((void**)&colh,   g_col_h);
    cudaGetSymbolAddress((void**)&parts,  g_partials);
    cudaGetSymbolAddress((void**)&partsh, g_partials_h);
    cudaGetSymbolAddress((void**)&zerob,  g_zero);
    cudaGetSymbolAddress((void**)&D1,     g_D1);
    cudaGetSymbolAddress((void**)&D2,     g_D2);
    cudaGetSymbolAddress((void**)&y0,     g_y0);
    cudaGetSymbolAddress((void**)&y2,     g_y2);
    cudaGetSymbolAddress((void**)&xfh, g_xfh); cudaGetSymbolAddress((void**)&xfl, g_xfl);
    cudaGetSymbolAddress((void**)&xhh, g_xhh); cudaGetSymbolAddress((void**)&xhl, g_xhl);
    cudaGetSymbolAddress((void**)&faH, g_faH); cudaGetSymbolAddress((void**)&faL, g_faL);
    cudaGetSymbolAddress((void**)&haH, g_haH); cudaGetSymbolAddress((void**)&haL, g_haL);
    cudaGetSymbolAddress((void**)&mhH, g_mhH); cudaGetSymbolAddress((void**)&mhL, g_mhL);
    cudaGetSymbolAddress((void**)&dualh, g_dualh); cudaGetSymbolAddress((void**)&duall, g_duall);
    cudaGetSymbolAddress((void**)&wrTh, g_wrTh); cudaGetSymbolAddress((void**)&wrTl, g_wrTl);
    cudaGetSymbolAddress((void**)&wlTh, g_wlTh); cudaGetSymbolAddress((void**)&wlTl, g_wlTl);
    cudaGetSymbolAddress((void**)&fhi, g_fhi); cudaGetSymbolAddress((void**)&flo, g_flo);

    const int SMEM_MAIN   = 81920;   // 2-stage mainloop
    const int SMEM_FUSE32 = 87040;   // FUSE (Wout projection)
    cudaFuncSetAttribute(mma_gemm<128, 2, 128, false, false, false, false>,
                         cudaFuncAttributeMaxDynamicSharedMemorySize, SMEM_MAIN);
    cudaFuncSetAttribute(mma_gemm<128, 2, 128, false, true, true, false>,
                         cudaFuncAttributeMaxDynamicSharedMemorySize, SMEM_MAIN);
    cudaFuncSetAttribute(mma_gemm<128, 2, 256, true, true, true, false>,
                         cudaFuncAttributeMaxDynamicSharedMemorySize, SMEM_MAIN);
    cudaFuncSetAttribute(mma_gemm<128, 2, 128, false, true, false, true>,
                         cudaFuncAttributeMaxDynamicSharedMemorySize, SMEM_FUSE32);

    const float* bl0 = bl + 0 * DIM;  const float* br0 = br + 0 * DIM;  // l0 flow
    const float* bl1 = bl + 1 * DIM;  const float* br1 = br + 1 * DIM;  // l0 host
    const float* bl2 = bl + 2 * DIM;  const float* br2 = br + 2 * DIM;  // l1 flow

    // ---- fork: all side streams branch from one recorded event --------------
    cudaEventRecord(evFork, 0);
    cudaStreamWaitEvent(s1, evFork, 0);
    cudaStreamWaitEvent(s2, evFork, 0);
    cudaStreamWaitEvent(s3, evFork, 0);

    // ---- s2: flow CSR [evCsrF] ----------------------------------------------
    build_csr(ehf_src, ehf_dst, N_FLOWN, rpf, colf, deg, parts, s2);
    cudaEventRecord(evCsrF, s2);

    // ---- s3: host CSR [evCsrH] ----------------------------------------------
    build_csr(efh_src, efh_dst, N_HOSTN, rph, colh, degh, partsh, s3);
    cudaEventRecord(evCsrH, s3);

    // ---- s0 head: prep + conv(x_host) [evPH], premul y0 (fp32) --------------
    prep_weights<<<(102400 + 255) / 256, 256>>>(
        Wl, Wr, W_out, dualh, duall, wrTh, wrTl, wlTh, wlTl, fhi, flo);
    conv_hl<<<(N_HOSTN * 32 + 255) / 256, 256>>>(x_host, xhh, xhl, N_HOSTN * 32);
    cudaEventRecord(evPH, 0);
    mma_gemm<128, 2, 128, false, false, false, false>
        <<<(N_HOSTN + 127) / 128, 256, SMEM_MAIN>>>(
        xhh, xhl, nullptr, nullptr, wlTh, wlTl, zerob, nullptr, nullptr,
        y0, nullptr, nullptr, nullptr, nullptr, nullptr, N_HOSTN);

    // ---- s1: conv(x_flow) [evConvF]; agg_h; gemm_h1; premul y2; agg_f2 ------
    conv_hl<<<(N_FLOWN * 32 + 255) / 256, 256, 0, s1>>>(x_flow, xfh, xfl, N_FLOWN * 32);
    cudaEventRecord(evConvF, s1);
    cudaStreamWaitEvent(s1, evCsrH, 0);
    aggregate_hl<<<(N_HOSTN + 7) / 8, 256, 0, s1>>>(xfh, xfl, rph, colh, mhH, mhL, N_HOSTN);
    cudaStreamWaitEvent(s1, evPH, 0);
    mma_gemm<128, 2, 256, true, true, true, false>
        <<<(N_HOSTN + 127) / 128, 256, SMEM_MAIN, s1>>>(
        mhH, mhL, xhh, xhl, dualh, duall, bl1, br1, nullptr,
        nullptr, haH, haL, nullptr, nullptr, nullptr, N_HOSTN);
    mma_gemm<128, 2, 128, false, false, false, false>
        <<<(N_HOSTN + 127) / 128, 256, SMEM_MAIN, s1>>>(
        haH, haL, nullptr, nullptr, wlTh + 128 * 128, wlTl + 128 * 128, zerob, nullptr,
        nullptr, y2, nullptr, nullptr, nullptr, nullptr, nullptr, N_HOSTN);
    cudaStreamWaitEvent(s1, evCsrF, 0);
    aggregate_flat<<<(N_FLOWN + 7) / 8, 256, 0, s1>>>(y2, rpf, colf, D2, N_FLOWN);
    cudaEventRecord(evS1done, s1);

    // ---- s0 tail: agg_f1 (flat on y0), flow layer-1 GEMM --------------------
    cudaStreamWaitEvent(0, evCsrF, 0);
    aggregate_flat<<<(N_FLOWN + 7) / 8, 256>>>(y0, rpf, colf, D1, N_FLOWN);
    cudaStreamWaitEvent(0, evConvF, 0);
    mma_gemm<128, 2, 128, false, true, true, false>
        <<<(N_FLOWN + 127) / 128, 256, SMEM_MAIN>>>(
        xfh, xfl, nullptr, nullptr, wrTh, wrTl, bl0, br0, D1,
        nullptr, faH, faL, nullptr, nullptr, nullptr, N_FLOWN);

    // ---- join: fused layer-2 flow GEMM (K=128 + addend) + output projection -
    cudaStreamWaitEvent(0, evS1done, 0);
    mma_gemm<128, 2, 128, false, true, false, true>
        <<<(N_FLOWN + 127) / 128, 256, SMEM_FUSE32>>>(
        faH, faL, nullptr, nullptr, wrTh + 128 * 128, wrTl + 128 * 128, bl2, br2, D2,
        out, nullptr, nullptr, fhi, flo, b_out, N_FLOWN);
}

// round 16
// speedup vs baseline: 1.0169x; 1.0169x over previous
#include <cuda_runtime.h>
#include <cuda_bf16.h>
#include <cstdint>

#define N_HOSTN 50000
#define N_FLOWN 200000
#define NEDGE   1000000
#define DIM     128
#define D_OUT   32

// ---------------- device scratch (static: no allocations allowed) ----------
__device__ int   g_deg[N_FLOWN + 1];
__device__ int   g_rowptr_f[N_FLOWN + 1];
__device__ int   g_rowptr_h[N_HOSTN + 1];
__device__ int   g_col_f[NEDGE];
__device__ int   g_col_h[NEDGE];
__device__ int   g_partials[256];
__device__ int   g_partials_h[256];
__device__ int   g_deg_h[N_HOSTN + 1];
__device__ float g_zero[DIM];            // zero bias (static zero-init)
// activations as bf16 hi/lo planes
__device__ __nv_bfloat16 g_xfh[(size_t)N_FLOWN * DIM], g_xfl[(size_t)N_FLOWN * DIM];
__device__ __nv_bfloat16 g_xhh[(size_t)N_HOSTN * DIM], g_xhl[(size_t)N_HOSTN * DIM];
__device__ __nv_bfloat16 g_faH[(size_t)N_FLOWN * DIM], g_faL[(size_t)N_FLOWN * DIM];
__device__ __nv_bfloat16 g_haH[(size_t)N_HOSTN * DIM], g_haL[(size_t)N_HOSTN * DIM];
__device__ __nv_bfloat16 g_mhH[(size_t)N_HOSTN * DIM], g_mhL[(size_t)N_HOSTN * DIM];
// pre-multiplied host features y = h @ Wl (per flow layer), fp32
__device__ float g_y0[(size_t)N_HOSTN * DIM];
__device__ float g_y2[(size_t)N_HOSTN * DIM];
// aggregated fp32 addends for flow GEMMs
__device__ float g_D1[(size_t)N_FLOWN * DIM];
__device__ float g_D2[(size_t)N_FLOWN * DIM];
// weights: host dual [128n][256k]; flow WrT/WlT [2][128n][128k]; Wout [32n][128k]
__device__ __nv_bfloat16 g_dualh[128 * 256], g_duall[128 * 256];
__device__ __nv_bfloat16 g_wrTh[2 * 128 * 128], g_wrTl[2 * 128 * 128];
__device__ __nv_bfloat16 g_wlTh[2 * 128 * 128], g_wlTl[2 * 128 * 128];
__device__ __nv_bfloat16 g_fhi[32 * 128], g_flo[32 * 128];

// ---------------- helpers ----------------------------------------------------
__device__ __forceinline__ uint32_t smem_u32(const void* p) {
    return (uint32_t)__cvta_generic_to_shared(p);
}

__device__ __forceinline__ void ldsm4(uint32_t* r, uint32_t addr) {
    asm volatile("ldmatrix.sync.aligned.m8n8.x4.shared.b16 {%0,%1,%2,%3}, [%4];"
                 : "=r"(r[0]), "=r"(r[1]), "=r"(r[2]), "=r"(r[3]) : "r"(addr));
}

__device__ __forceinline__ void mma_bf16(float* c, const uint32_t* a, const uint32_t* b) {
    asm volatile(
        "mma.sync.aligned.m16n8k16.row.col.f32.bf16.bf16.f32 "
        "{%0,%1,%2,%3}, {%4,%5,%6,%7}, {%8,%9}, {%0,%1,%2,%3};"
        : "+f"(c[0]), "+f"(c[1]), "+f"(c[2]), "+f"(c[3])
        : "r"(a[0]), "r"(a[1]), "r"(a[2]), "r"(a[3]), "r"(b[0]), "r"(b[1]));
}

__device__ __forceinline__ uint32_t pack2(__nv_bfloat16 a, __nv_bfloat16 b) {
    uint32_t lo = (uint32_t)__bfloat16_as_ushort(a);
    uint32_t hi = (uint32_t)__bfloat16_as_ushort(b);
    return lo | (hi << 16);
}

__device__ __forceinline__ float2 bf2f(uint32_t u) {
    float2 r;
    r.x = __bfloat162float(__ushort_as_bfloat16((unsigned short)(u & 0xffff)));
    r.y = __bfloat162float(__ushort_as_bfloat16((unsigned short)(u >> 16)));
    return r;
}

__device__ __forceinline__ void cpa16(uint32_t dst, const void* src, int szbytes) {
    asm volatile("cp.async.cg.shared.global [%0], [%1], 16, %2;"
                 :: "r"(dst), "l"(src), "r"(szbytes));
}

// ---------------- small utility kernels ------------------------------------
__global__ void zero_kernel(int* p, int n) {
    int i = blockIdx.x * blockDim.x + threadIdx.x;
    if (i < n) p[i] = 0;
}

__global__ void hist_kernel(const int* __restrict__ dst, int* __restrict__ deg, int n) {
    for (int i = blockIdx.x * blockDim.x + threadIdx.x; i < n; i += gridDim.x * blockDim.x)
        atomicAdd(&deg[dst[i]], 1);
}

__global__ void scan_blocks(const int* __restrict__ in, int* __restrict__ out,
                            int* __restrict__ partials, int n) {
    __shared__ int sh[256];
    int t = threadIdx.x;
    int base = blockIdx.x * 1024 + t * 4;
    int v0 = (base + 0 < n) ? in[base + 0] : 0;
    int v1 = (base + 1 < n) ? in[base + 1] : 0;
    int v2 = (base + 2 < n) ? in[base + 2] : 0;
    int v3 = (base + 3 < n) ? in[base + 3] : 0;
    int s = v0 + v1 + v2 + v3;
    sh[t] = s;
    __syncthreads();
    for (int off = 1; off < 256; off <<= 1) {
        int y = (t >= off) ? sh[t - off] : 0;
        __syncthreads();
        sh[t] += y;
        __syncthreads();
    }
    int excl = sh[t] - s;
    if (t == 255) partials[blockIdx.x] = sh[255];
    int run = excl;
    if (base + 0 < n) out[base + 0] = run; run += v0;
    if (base + 1 < n) out[base + 1] = run; run += v1;
    if (base + 2 < n) out[base + 2] = run; run += v2;
    if (base + 3 < n) out[base + 3] = run;
}

__global__ void scan_partials(int* partials, int nb) {
    __shared__ int sh[256];
    int t = threadIdx.x;
    int v = (t < nb) ? partials[t] : 0;
    sh[t] = v;
    __syncthreads();
    for (int off = 1; off < 256; off <<= 1) {
        int y = (t >= off) ? sh[t - off] : 0;
        __syncthreads();
        sh[t] += y;
        __syncthreads();
    }
    if (t < nb) partials[t] = sh[t] - v;
}

__global__ void scan_add(int* __restrict__ out, const int* __restrict__ partials, int n) {
    for (int i = blockIdx.x * blockDim.x + threadIdx.x; i < n; i += gridDim.x * blockDim.x)
        out[i] += partials[i >> 10];
}

__global__ void fill_kernel(const int* __restrict__ src, const int* __restrict__ dst,
                            const int* __restrict__ rowptr, int* __restrict__ cursor,
                            int* __restrict__ col, int n) {
    for (int e = blockIdx.x * blockDim.x + threadIdx.x; e < n; e += gridDim.x * blockDim.x) {
        int d = dst[e];
        int p = rowptr[d] + atomicAdd(&cursor[d], 1);
        col[p] = src[e];
    }
}

// fp32 [N][128] -> bf16 hi/lo planes
__global__ void conv_hl(const float* __restrict__ x, __nv_bfloat16* __restrict__ hi,
                        __nv_bfloat16* __restrict__ lo, int nq) {
    int i = blockIdx.x * blockDim.x + threadIdx.x;
    if (i >= nq) return;
    float4 v = ((const float4*)x)[i];
    __nv_bfloat16 h0 = __float2bfloat16(v.x), h1 = __float2bfloat16(v.y);
    __nv_bfloat16 h2 = __float2bfloat16(v.z), h3 = __float2bfloat16(v.w);
    __nv_bfloat16 l0 = __float2bfloat16(v.x - __bfloat162float(h0));
    __nv_bfloat16 l1 = __float2bfloat16(v.y - __bfloat162float(h1));
    __nv_bfloat16 l2 = __float2bfloat16(v.z - __bfloat162float(h2));
    __nv_bfloat16 l3 = __float2bfloat16(v.w - __bfloat162float(h3));
    ((uint2*)hi)[i] = make_uint2(pack2(h0, h1), pack2(h2, h3));
    ((uint2*)lo)[i] = make_uint2(pack2(l0, l1), pack2(l2, l3));
}

// transposed bf16 hi/lo weight planes
__global__ void prep_weights(const float* __restrict__ Wl, const float* __restrict__ Wr,
                             const float* __restrict__ W_out,
                             __nv_bfloat16* __restrict__ dualh, __nv_bfloat16* __restrict__ duall,
                             __nv_bfloat16* __restrict__ wrTh, __nv_bfloat16* __restrict__ wrTl,
                             __nv_bfloat16* __restrict__ wlTh, __nv_bfloat16* __restrict__ wlTl,
                             __nv_bfloat16* __restrict__ fhi, __nv_bfloat16* __restrict__ flo) {
    int i = blockIdx.x * blockDim.x + threadIdx.x;
    if (i >= 102400) return;
    float v;
    __nv_bfloat16* dh;
    __nv_bfloat16* dl;
    int idx;
    if (i < 32768) {
        int n = i >> 8, k = i & 255;
        if (k < DIM) v = Wl[((size_t)1 * DIM + k) * DIM + n];
        else         v = Wr[((size_t)1 * DIM + (k - DIM)) * DIM + n];
        dh = dualh; dl = duall; idx = i;
    } else if (i < 65536) {
        int r = i - 32768;
        int g = r >> 14, rr = r & 16383;
        int n = rr >> 7, k = rr & 127;
        v = Wr[((size_t)(g * 2 + 0) * DIM + k) * DIM + n];
        dh = wrTh; dl = wrTl; idx = r;
    } else if (i < 98304) {
        int r = i - 65536;
        int g = r >> 14, rr = r & 16383;
        int n = rr >> 7, k = rr & 127;
        v = Wl[((size_t)(g * 2 + 0) * DIM + k) * DIM + n];
        dh = wlTh; dl = wlTl; idx = r;
    } else {
        int r = i - 98304;
        int n = r >> 7, k = r & 127;
        v = W_out[(size_t)k * D_OUT + n];
        dh = fhi; dl = flo; idx = r;
    }
    __nv_bfloat16 h = __float2bfloat16(v);
    dh[idx] = h;
    dl[idx] = __float2bfloat16(v - __bfloat162float(h));
}

// ---------------- mean aggregation of RAW fp32 rows -> bf16 hi/lo planes -----
// one warp per dst row; lane owns 4 floats (32 x float4 = 128 feats); no shfl.
__global__ void aggregate_raw(const float* __restrict__ x,
                              const int* __restrict__ rowptr,
                              const int* __restrict__ col,
                              __nv_bfloat16* __restrict__ mh,
                              __nv_bfloat16* __restrict__ ml, int ndst) {
    int warp = (blockIdx.x * blockDim.x + threadIdx.x) >> 5;
    int lane = threadIdx.x & 31;
    if (warp >= ndst) return;
    int start = rowptr[warp];
    int end   = rowptr[warp + 1];
    const float4* P = (const float4*)x;
    float a0 = 0.f, a1 = 0.f, a2 = 0.f, a3 = 0.f;
    int e = start;
    for (; e + 1 < end; e += 2) {
        int s0 = __ldg(&col[e]);
        int s1 = __ldg(&col[e + 1]);
        float4 v0 = __ldg(&P[(size_t)s0 * 32 + lane]);
        float4 v1 = __ldg(&P[(size_t)s1 * 32 + lane]);
        a0 += v0.x + v1.x; a1 += v0.y + v1.y;
        a2 += v0.z + v1.z; a3 += v0.w + v1.w;
    }
    if (e < end) {
        int s0 = __ldg(&col[e]);
        float4 v0 = __ldg(&P[(size_t)s0 * 32 + lane]);
        a0 += v0.x; a1 += v0.y; a2 += v0.z; a3 += v0.w;
    }
    int deg = end - start;
    float inv = 1.f / (float)(deg > 1 ? deg : 1);
    a0 *= inv; a1 *= inv; a2 *= inv; a3 *= inv;
    __nv_bfloat16 h0 = __float2bfloat16(a0), h1 = __float2bfloat16(a1);
    __nv_bfloat16 h2 = __float2bfloat16(a2), h3 = __float2bfloat16(a3);
    __nv_bfloat16 l0 = __float2bfloat16(a0 - __bfloat162float(h0));
    __nv_bfloat16 l1 = __float2bfloat16(a1 - __bfloat162float(h1));
    __nv_bfloat16 l2 = __float2bfloat16(a2 - __bfloat162float(h2));
    __nv_bfloat16 l3 = __float2bfloat16(a3 - __bfloat162float(h3));
    ((uint2*)mh)[(size_t)warp * 32 + lane] = make_uint2(pack2(h0, h1), pack2(h2, h3));
    ((uint2*)ml)[(size_t)warp * 32 + lane] = make_uint2(pack2(l0, l1), pack2(l2, l3));
}

// ---------------- mean aggregation, flat fp32 gather -> fp32 addend ----------
__global__ void aggregate_flat(const float* __restrict__ y,
                               const int* __restrict__ rowptr,
                               const int* __restrict__ col,
                               float* __restrict__ D, int ndst) {
    int warp = (blockIdx.x * blockDim.x + threadIdx.x) >> 5;
    int lane = threadIdx.x & 31;
    if (warp >= ndst) return;
    int start = rowptr[warp];
    int end   = rowptr[warp + 1];
    const float4* P = (const float4*)y;
    float a0 = 0.f, a1 = 0.f, a2 = 0.f, a3 = 0.f;
    int e = start;
    for (; e + 1 < end; e += 2) {
        int s0 = __ldg(&col[e]);
        int s1 = __ldg(&col[e + 1]);
        float4 v0 = __ldg(&P[(size_t)s0 * 32 + lane]);
        float4 v1 = __ldg(&P[(size_t)s1 * 32 + lane]);
        a0 += v0.x + v1.x; a1 += v0.y + v1.y;
        a2 += v0.z + v1.z; a3 += v0.w + v1.w;
    }
    if (e < end) {
        int s0 = __ldg(&col[e]);
        float4 v0 = __ldg(&P[(size_t)s0 * 32 + lane]);
        a0 += v0.x; a1 += v0.y; a2 += v0.z; a3 += v0.w;
    }
    int deg = end - start;
    float inv = 1.f / (float)(deg > 1 ? deg : 1);
    ((float4*)D)[(size_t)warp * 32 + lane] = make_float4(a0 * inv, a1 * inv,
                                                         a2 * inv, a3 * inv);
}

// ---------------- mma.sync bf16 GEMM, 3-pass hi/lo, cp.async 2-stage ---------
// AD: optional fp32 [M][128] addend before act. FUSE: second GEMM @ FW[32][128].
template <int BN, int WROWS, int KTOT, bool DUAL, bool ACT, bool WHL, bool FUSE>
__global__ __launch_bounds__(256) void mma_gemm(
    const __nv_bfloat16* __restrict__ Ah0, const __nv_bfloat16* __restrict__ Al0,
    const __nv_bfloat16* __restrict__ Ah1, const __nv_bfloat16* __restrict__ Al1,
    const __nv_bfloat16* __restrict__ Bh, const __nv_bfloat16* __restrict__ Bl,
    const float* __restrict__ bias0, const float* __restrict__ bias1,
    const float* __restrict__ AD,
    float* __restrict__ C, __nv_bfloat16* __restrict__ OutH,
    __nv_bfloat16* __restrict__ OutL,
    const __nv_bfloat16* __restrict__ FWh, const __nv_bfloat16* __restrict__ FWl,
    const float* __restrict__ bout, int M)
{
    constexpr int WCOLS  = 8 / WROWS;
    constexpr int WARP_M = 128 / WROWS;
    constexpr int WARP_N = BN / WCOLS;
    constexpr int TM = WARP_M / 16;
    constexpr int TN = WARP_N / 8;
    constexpr int AS = 40;
    constexpr int A_PLANE = 128 * AS * 2;
    constexpr int B_PLANE = BN * AS * 2;
    constexpr int STAGE = 2 * A_PLANE + 2 * B_PLANE;
    constexpr int NK = KTOT / 32;
    constexpr int PC = 68;

    extern __shared__ char dynsmem[];
    __shared__ float s_bias[BN];

    const int tid  = threadIdx.x;
    const int wid  = tid >> 5;
    const int lane = tid & 31;
    const int wrow = wid / WCOLS;
    const int wcol = wid % WCOLS;
    const int rowbase = blockIdx.x * 128;
    const uint32_t sb = smem_u32(dynsmem);

    if (tid < BN) s_bias[tid] = bias0[tid] + (bias1 ? bias1[tid] : 0.f);

    float acc[TM][TN][4];
#pragma unroll
    for (int i = 0; i < TM; i++)
#pragma unroll
        for (int j = 0; j < TN; j++)
#pragma unroll
            for (int q = 0; q < 4; q++) acc[i][j][q] = 0.f;

    uint32_t aoff[TM][2];
#pragma unroll
    for (int i = 0; i < TM; i++)
#pragma unroll
        for (int ks = 0; ks < 2; ks++) {
            int row = wrow * WARP_M + i * 16 + (lane & 15);
            int colk = ks * 16 + (lane >> 4) * 8;
            aoff[i][ks] = (uint32_t)(row * AS + colk) * 2;
        }
    uint32_t boff[TN / 2][2];
#pragma unroll
    for (int jj = 0; jj < TN / 2; jj++)
#pragma unroll
        for (int ks = 0; ks < 2; ks++) {
            int n = wcol * WARP_N + jj * 16 + (lane & 7) + ((lane >> 4) & 1) * 8;
            int k = ks * 16 + ((lane >> 3) & 1) * 8;
            boff[jj][ks] = (uint32_t)(n * AS + k) * 2;
        }

    auto load_stage = [&](int s, int k0) {
        uint32_t su = sb + (uint32_t)s * STAGE;
        const __nv_bfloat16* A_h = Ah0;
        const __nv_bfloat16* A_l = Al0;
        int ka = k0;
        if (DUAL && k0 >= DIM) { A_h = Ah1; A_l = Al1; ka = k0 - DIM; }
#pragma unroll
        for (int idx = tid; idx < 512; idx += 256) {
            int r = idx >> 2, q = idx & 3;
            int row = rowbase + r;
            int sz = (row < M) ? 16 : 0;
            int crow = row < M ? row : (M - 1);
            uint32_t d = su + (uint32_t)(r * AS + q * 8) * 2;
            cpa16(d, A_h + (size_t)crow * DIM + ka + q * 8, sz);
            cpa16(d + A_PLANE, A_l + (size_t)crow * DIM + ka + q * 8, sz);
        }
#pragma unroll
        for (int idx = tid; idx < BN * 4; idx += 256) {
            int n = idx >> 2, q = idx & 3;
            uint32_t d = su + 2 * A_PLANE + (uint32_t)(n * AS + q * 8) * 2;
            cpa16(d, Bh + (size_t)n * KTOT + k0 + q * 8, 16);
            cpa16(d + B_PLANE, Bl + (size_t)n * KTOT + k0 + q * 8, 16);
        }
        asm volatile("cp.async.commit_group;");
    };

    load_stage(0, 0);

    for (int c = 0; c < NK; c++) {
        if (c + 1 < NK) {
            load_stage((c + 1) & 1, (c + 1) * 32);
            asm volatile("cp.async.wait_group 1;");
        } else {
            asm volatile("cp.async.wait_group 0;");
        }
        __syncthreads();

        uint32_t su = sb + (uint32_t)(c & 1) * STAGE;
        const uint32_t uAh = su;
        const uint32_t uAl = su + A_PLANE;
        const uint32_t uBh = su + 2 * A_PLANE;
        const uint32_t uBl = uBh + B_PLANE;

#pragma unroll
        for (int ks = 0; ks < 2; ks++) {
            uint32_t ah[TM][4], al[TM][4];
#pragma unroll
            for (int i = 0; i < TM; i++) {
                ldsm4(ah[i], uAh + aoff[i][ks]);
                ldsm4(al[i], uAl + aoff[i][ks]);
            }
            uint32_t bh[TN][2], bl_[TN][2];
#pragma unroll
            for (int jj = 0; jj < TN / 2; jj++) {
                uint32_t r4[4];
                ldsm4(r4, uBh + boff[jj][ks]);
                bh[2 * jj][0] = r4[0]; bh[2 * jj][1] = r4[1];
                bh[2 * jj + 1][0] = r4[2]; bh[2 * jj + 1][1] = r4[3];
                ldsm4(r4, uBl + boff[jj][ks]);
                bl_[2 * jj][0] = r4[0]; bl_[2 * jj][1] = r4[1];
                bl_[2 * jj + 1][0] = r4[2]; bl_[2 * jj + 1][1] = r4[3];
            }
#pragma unroll
            for (int i = 0; i < TM; i++)
#pragma unroll
                for (int j = 0; j < TN; j++) {
                    mma_bf16(acc[i][j], ah[i], bh[j]);
                    mma_bf16(acc[i][j], ah[i], bl_[j]);
                    mma_bf16(acc[i][j], al[i], bh[j]);
                }
        }
        __syncthreads();
    }

    if (!FUSE) {
#pragma unroll
        for (int i = 0; i < TM; i++) {
#pragma unroll
            for (int j = 0; j < TN; j++) {
                int row0 = rowbase + wrow * WARP_M + i * 16 + (lane >> 2);
                int colb = wcol * WARP_N + j * 8 + (lane & 3) * 2;
                float b0 = s_bias[colb], b1 = s_bias[colb + 1];
#pragma unroll
                for (int h = 0; h < 2; h++) {
                    int row = row0 + h * 8;
                    if (row < M) {
                        float dx = 0.f, dy = 0.f;
                        if (AD) {
                            float2 dv = *(const float2*)&AD[(size_t)row * DIM + colb];
                            dx = dv.x; dy = dv.y;
                        }
                        float vx = acc[i][j][2 * h + 0] + b0 + dx;
                        float vy = acc[i][j][2 * h + 1] + b1 + dy;
                        if (ACT) {
                            vx = vx > 0.f ? vx : 0.01f * vx;
                            vy = vy > 0.f ? vy : 0.01f * vy;
                        }
                        if (WHL) {
                            __nv_bfloat16 hx = __float2bfloat16(vx);
                            __nv_bfloat16 hy = __float2bfloat16(vy);
                            __nv_bfloat16 lx = __float2bfloat16(vx - __bfloat162float(hx));
                            __nv_bfloat16 ly = __float2bfloat16(vy - __bfloat162float(hy));
                            *(uint32_t*)&OutH[(size_t)row * BN + colb] = pack2(hx, hy);
                            *(uint32_t*)&OutL[(size_t)row * BN + colb] = pack2(lx, ly);
                        } else {
                            *(float2*)&C[(size_t)row * BN + colb] = make_float2(vx, vy);
                        }
                    }
                }
            }
        }
    } else {
        // ---- fused output projection: act-tile (smem, bf16 hi/lo pairs) @ Wout
        uint32_t* sC_hi = (uint32_t*)dynsmem;          // [128][PC]
        uint32_t* sC_lo = sC_hi + 128 * PC;
        uint32_t* sW_hi = sC_lo + 128 * PC;            // [32][PC]
        uint32_t* sW_lo = sW_hi + 32 * PC;

        for (int idx = tid; idx < 32 * 64; idx += 256) {
            int n = idx >> 6, kp = idx & 63;
            sW_hi[n * PC + kp] = ((const uint32_t*)FWh)[n * 64 + kp];
            sW_lo[n * PC + kp] = ((const uint32_t*)FWl)[n * 64 + kp];
        }
#pragma unroll
        for (int i = 0; i < TM; i++) {
#pragma unroll
            for (int j = 0; j < TN; j++) {
                int lrow0 = wrow * WARP_M + i * 16 + (lane >> 2);
                int colb = wcol * WARP_N + j * 8 + (lane & 3) * 2;
                int pair = colb >> 1;
                float b0 = s_bias[colb], b1 = s_bias[colb + 1];
#pragma unroll
                for (int h = 0; h < 2; h++) {
                    int lrow = lrow0 + h * 8;
                    int grow = rowbase + lrow;
                    float dx = 0.f, dy = 0.f;
                    if (AD && grow < M) {
                        float2 dv = *(const float2*)&AD[(size_t)grow * DIM + colb];
                        dx = dv.x; dy = dv.y;
                    }
                    float vx = acc[i][j][2 * h + 0] + b0 + dx;
                    float vy = acc[i][j][2 * h + 1] + b1 + dy;
                    vx = vx > 0.f ? vx : 0.01f * vx;
                    vy = vy > 0.f ? vy : 0.01f * vy;
                    __nv_bfloat16 hx = __float2bfloat16(vx);
                    __nv_bfloat16 hy = __float2bfloat16(vy);
                    __nv_bfloat16 lx = __float2bfloat16(vx - __bfloat162float(hx));
                    __nv_bfloat16 ly = __float2bfloat16(vy - __bfloat162float(hy));
                    sC_hi[lrow * PC + pair] = pack2(hx, hy);
                    sC_lo[lrow * PC + pair] = pack2(lx, ly);
                }
            }
        }
        __syncthreads();

        const int g = lane >> 2, tig = lane & 3;
        const int w2row = wid * 16;
        float acc2[4][4];
#pragma unroll
        for (int j = 0; j < 4; j++)
#pragma unroll
            for (int q = 0; q < 4; q++) acc2[j][q] = 0.f;

#pragma unroll
        for (int ks = 0; ks < 8; ks++) {
            int ro  = (w2row + g) * PC + ks * 8 + tig;
            int ro8 = ro + 8 * PC;
            uint32_t ah[4] = {sC_hi[ro], sC_hi[ro8], sC_hi[ro + 4], sC_hi[ro8 + 4]};
            uint32_t al[4] = {sC_lo[ro], sC_lo[ro8], sC_lo[ro + 4], sC_lo[ro8 + 4]};
#pragma unroll
            for (int j = 0; j < 4; j++) {
                int bo = (j * 8 + g) * PC + ks * 8 + tig;
                uint32_t bh[2]  = {sW_hi[bo], sW_hi[bo + 4]};
                uint32_t bl2[2] = {sW_lo[bo], sW_lo[bo + 4]};
                mma_bf16(acc2[j], ah, bh);
                mma_bf16(acc2[j], ah, bl2);
                mma_bf16(acc2[j], al, bh);
            }
        }
#pragma unroll
        for (int j = 0; j < 4; j++) {
            int colo = j * 8 + tig * 2;
            float bo0 = bout[colo], bo1 = bout[colo + 1];
            int r0 = rowbase + w2row + g;
            if (r0 < M)
                *(float2*)&C[(size_t)r0 * D_OUT + colo] =
                    make_float2(acc2[j][0] + bo0, acc2[j][1] + bo1);
            int r1 = r0 + 8;
            if (r1 < M)
                *(float2*)&C[(size_t)r1 * D_OUT + colo] =
                    make_float2(acc2[j][2] + bo0, acc2[j][3] + bo1);
        }
    }
}

// ---------------- host side -------------------------------------------------
static void build_csr(const int* src, const int* dst, int ndst,
                      int* rowptr, int* col, int* deg, int* parts, cudaStream_t st) {
    int n1 = ndst + 1;
    zero_kernel<<<(n1 + 255) / 256, 256, 0, st>>>(deg, n1);
    hist_kernel<<<2048, 256, 0, st>>>(dst, deg, NEDGE);
    int nb = (n1 + 1023) / 1024;
    scan_blocks<<<nb, 256, 0, st>>>(deg, rowptr, parts, n1);
    scan_partials<<<1, 256, 0, st>>>(parts, nb);
    scan_add<<<nb, 256, 0, st>>>(rowptr, parts, n1);
    zero_kernel<<<(n1 + 255) / 256, 256, 0, st>>>(deg, n1);
    fill_kernel<<<2048, 256, 0, st>>>(src, dst, rowptr, deg, col, NEDGE);
}

extern "C" void kernel_launch(void* const* d_in, const int* in_sizes, int n_in,
                              void* d_out, int out_size) {
    (void)in_sizes; (void)n_in; (void)out_size;
    const float* x_host  = (const float*)d_in[0];
    const float* x_flow  = (const float*)d_in[1];
    const int*   ehf_src = (const int*)d_in[2];
    const int*   ehf_dst = (const int*)d_in[3];
    const int*   efh_src = (const int*)d_in[4];
    const int*   efh_dst = (const int*)d_in[5];
    const float* Wl      = (const float*)d_in[6];
    const float* bl      = (const float*)d_in[7];
    const float* Wr      = (const float*)d_in[8];
    const float* br      = (const float*)d_in[9];
    const float* W_out   = (const float*)d_in[10];
    const float* b_out   = (const float*)d_in[11];
    float* out = (float*)d_out;

    static bool inited = false;
    static cudaStream_t s1, s2, s3;
    static cudaEvent_t evFork, evPH, evConvF, evCsrF, evCsrH, evS1done;
    if (!inited) {
        cudaStreamCreateWithFlags(&s1, cudaStreamNonBlocking);
        cudaStreamCreateWithFlags(&s2, cudaStreamNonBlocking);
        cudaStreamCreateWithFlags(&s3, cudaStreamNonBlocking);
        cudaEventCreateWithFlags(&evFork,   cudaEventDisableTiming);
        cudaEventCreateWithFlags(&evPH,     cudaEventDisableTiming);
        cudaEventCreateWithFlags(&evConvF,  cudaEventDisableTiming);
        cudaEventCreateWithFlags(&evCsrF,   cudaEventDisableTiming);
        cudaEventCreateWithFlags(&evCsrH,   cudaEventDisableTiming);
        cudaEventCreateWithFlags(&evS1done, cudaEventDisableTiming);
        inited = true;
    }

    int *deg, *degh, *rpf, *rph, *colf, *colh, *parts, *partsh;
    float *zerob, *D1, *D2, *y0, *y2;
    __nv_bfloat16 *xfh, *xfl, *xhh, *xhl, *faH, *faL, *haH, *haL, *mhH, *mhL;
    __nv_bfloat16 *dualh, *duall, *wrTh, *wrTl, *wlTh, *wlTl, *fhi, *flo;
    cudaGetSymbolAddress((void**)&deg,    g_deg);
    cudaGetSymbolAddress((void**)&degh,   g_deg_h);
    cudaGetSymbolAddress((void**)&rpf,    g_rowptr_f);
    cudaGetSymbolAddress((void**)&rph,    g_rowptr_h);
    cudaGetSymbolAddress((void**)&colf,   g_col_f);
    cudaGetSymbolAddress((void**)&colh,   g_col_h);
    cudaGetSymbolAddress((void**)&parts,  g_partials);
    cudaGetSymbolAddress((void**)&partsh, g_partials_h);
    cudaGetSymbolAddress((void**)&zerob,  g_zero);
    cudaGetSymbolAddress((void**)&D1,     g_D1);
    cudaGetSymbolAddress((void**)&D2,     g_D2);
    cudaGetSymbolAddress((void**)&y0,     g_y0);
    cudaGetSymbolAddress((void**)&y2,     g_y2);
    cudaGetSymbolAddress((void**)&xfh, g_xfh); cudaGetSymbolAddress((void**)&xfl, g_xfl);
    cudaGetSymbolAddress((void**)&xhh, g_xhh); cudaGetSymbolAddress((void**)&xhl, g_xhl);
    cudaGetSymbolAddress((void**)&faH, g_faH); cudaGetSymbolAddress((void**)&faL, g_faL);
    cudaGetSymbolAddress((void**)&haH, g_haH); cudaGetSymbolAddress((void**)&haL, g_haL);
    cudaGetSymbolAddress((void**)&mhH, g_mhH); cudaGetSymbolAddress((void**)&mhL, g_mhL);
    cudaGetSymbolAddress((void**)&dualh, g_dualh); cudaGetSymbolAddress((void**)&duall, g_duall);
    cudaGetSymbolAddress((void**)&wrTh, g_wrTh); cudaGetSymbolAddress((void**)&wrTl, g_wrTl);
    cudaGetSymbolAddress((void**)&wlTh, g_wlTh); cudaGetSymbolAddress((void**)&wlTl, g_wlTl);
    cudaGetSymbolAddress((void**)&fhi, g_fhi); cudaGetSymbolAddress((void**)&flo, g_flo);

    const int SMEM_MAIN   = 81920;   // 2-stage mainloop
    const int SMEM_FUSE32 = 87040;   // FUSE (Wout projection)
    cudaFuncSetAttribute(mma_gemm<128, 2, 128, false, false, false, false>,
                         cudaFuncAttributeMaxDynamicSharedMemorySize, SMEM_MAIN);
    cudaFuncSetAttribute(mma_gemm<128, 2, 128, false, true, true, false>,
                         cudaFuncAttributeMaxDynamicSharedMemorySize, SMEM_MAIN);
    cudaFuncSetAttribute(mma_gemm<128, 2, 256, true, true, true, false>,
                         cudaFuncAttributeMaxDynamicSharedMemorySize, SMEM_MAIN);
    cudaFuncSetAttribute(mma_gemm<128, 2, 128, false, true, false, true>,
                         cudaFuncAttributeMaxDynamicSharedMemorySize, SMEM_FUSE32);

    const float* bl0 = bl + 0 * DIM;  const float* br0 = br + 0 * DIM;  // l0 flow
    const float* bl1 = bl + 1 * DIM;  const float* br1 = br + 1 * DIM;  // l0 host
    const float* bl2 = bl + 2 * DIM;  const float* br2 = br + 2 * DIM;  // l1 flow

    // ---- fork: all side streams branch from one recorded event --------------
    cudaEventRecord(evFork, 0);
    cudaStreamWaitEvent(s1, evFork, 0);
    cudaStreamWaitEvent(s2, evFork, 0);
    cudaStreamWaitEvent(s3, evFork, 0);

    // ---- s2: flow CSR [evCsrF], then conv(x_flow) [evConvF] -----------------
    build_csr(ehf_src, ehf_dst, N_FLOWN, rpf, colf, deg, parts, s2);
    cudaEventRecord(evCsrF, s2);
    conv_hl<<<(N_FLOWN * 32 + 255) / 256, 256, 0, s2>>>(x_flow, xfh, xfl, N_FLOWN * 32);
    cudaEventRecord(evConvF, s2);

    // ---- s3: host CSR [evCsrH] ----------------------------------------------
    build_csr(efh_src, efh_dst, N_HOSTN, rph, colh, degh, partsh, s3);
    cudaEventRecord(evCsrH, s3);

    // ---- s0 head: prep + conv(x_host) [evPH], premul y0 (fp32) --------------
    prep_weights<<<(102400 + 255) / 256, 256>>>(
        Wl, Wr, W_out, dualh, duall, wrTh, wrTl, wlTh, wlTl, fhi, flo);
    conv_hl<<<(N_HOSTN * 32 + 255) / 256, 256>>>(x_host, xhh, xhl, N_HOSTN * 32);
    cudaEventRecord(evPH, 0);
    mma_gemm<128, 2, 128, false, false, false, false>
        <<<(N_HOSTN + 127) / 128, 256, SMEM_MAIN>>>(
        xhh, xhl, nullptr, nullptr, wlTh, wlTl, zerob, nullptr, nullptr,
        y0, nullptr, nullptr, nullptr, nullptr, nullptr, N_HOSTN);

    // ---- s1: agg_h from RAW x_flow (no conv dependency!); gemm_h1; y2; agg_f2
    cudaStreamWaitEvent(s1, evCsrH, 0);
    aggregate_raw<<<(N_HOSTN + 7) / 8, 256, 0, s1>>>(x_flow, rph, colh, mhH, mhL, N_HOSTN);
    cudaStreamWaitEvent(s1, evPH, 0);
    mma_gemm<128, 2, 256, true, true, true, false>
        <<<(N_HOSTN + 127) / 128, 256, SMEM_MAIN, s1>>>(
        mhH, mhL, xhh, xhl, dualh, duall, bl1, br1, nullptr,
        nullptr, haH, haL, nullptr, nullptr, nullptr, N_HOSTN);
    mma_gemm<128, 2, 128, false, false, false, false>
        <<<(N_HOSTN + 127) / 128, 256, SMEM_MAIN, s1>>>(
        haH, haL, nullptr, nullptr, wlTh + 128 * 128, wlTl + 128 * 128, zerob, nullptr,
        nullptr, y2, nullptr, nullptr, nullptr, nullptr, nullptr, N_HOSTN);
    cudaStreamWaitEvent(s1, evCsrF, 0);
    aggregate_flat<<<(N_FLOWN + 7) / 8, 256, 0, s1>>>(y2, rpf, colf, D2, N_FLOWN);
    cudaEventRecord(evS1done, s1);

    // ---- s0 tail: agg_f1 (flat on y0), flow layer-1 GEMM --------------------
    cudaStreamWaitEvent(0, evCsrF, 0);
    aggregate_flat<<<(N_FLOWN + 7) / 8, 256>>>(y0, rpf, colf, D1, N_FLOWN);
    cudaStreamWaitEvent(0, evConvF, 0);
    mma_gemm<128, 2, 128, false, true, true, false>
        <<<(N_FLOWN + 127) / 128, 256, SMEM_MAIN>>>(
        xfh, xfl, nullptr, nullptr, wrTh, wrTl, bl0, br0, D1,
        nullptr, faH, faL, nullptr, nullptr, nullptr, N_FLOWN);

    // ---- join: fused layer-2 flow GEMM (K=128 + addend) + output projection -
    cudaStreamWaitEvent(0, evS1done, 0);
    mma_gemm<128, 2, 128, false, true, false, true>
        <<<(N_FLOWN + 127) / 128, 256, SMEM_FUSE32>>>(
        faH, faL, nullptr, nullptr, wrTh + 128 * 128, wrTl + 128 * 128, bl2, br2, D2,
        out, nullptr, nullptr, fhi, flo, b_out, N_FLOWN);
}

// round 17
// speedup vs baseline: 1.0338x; 1.0166x over previous
#include <cuda_runtime.h>
#include <cuda_bf16.h>
#include <cstdint>

#define N_HOSTN 50000
#define N_FLOWN 200000
#define NEDGE   1000000
#define DIM     128
#define D_OUT   32

// ---------------- device scratch (static: no allocations allowed) ----------
__device__ int   g_deg[N_FLOWN + 1];
__device__ int   g_rowptr_f[N_FLOWN + 1];
__device__ int   g_rowptr_h[N_HOSTN + 1];
__device__ int   g_col_f[NEDGE];
__device__ int   g_col_h[NEDGE];
__device__ int   g_partials[256];
__device__ int   g_partials_h[256];
__device__ int   g_deg_h[N_HOSTN + 1];
__device__ float g_zero[DIM];            // zero bias (static zero-init)
// activations as bf16 hi/lo planes (host side + layer-1 flow output)
__device__ __nv_bfloat16 g_xhh[(size_t)N_HOSTN * DIM], g_xhl[(size_t)N_HOSTN * DIM];
__device__ __nv_bfloat16 g_faH[(size_t)N_FLOWN * DIM], g_faL[(size_t)N_FLOWN * DIM];
__device__ __nv_bfloat16 g_haH[(size_t)N_HOSTN * DIM], g_haL[(size_t)N_HOSTN * DIM];
__device__ __nv_bfloat16 g_mhH[(size_t)N_HOSTN * DIM], g_mhL[(size_t)N_HOSTN * DIM];
// pre-multiplied host features y = h @ Wl (per flow layer), fp32
__device__ float g_y0[(size_t)N_HOSTN * DIM];
__device__ float g_y2[(size_t)N_HOSTN * DIM];
// aggregated fp32 addends for flow GEMMs
__device__ float g_D1[(size_t)N_FLOWN * DIM];
__device__ float g_D2[(size_t)N_FLOWN * DIM];
// weights: host dual [128n][256k]; flow WrT/WlT [2][128n][128k]; Wout [32n][128k]
__device__ __nv_bfloat16 g_dualh[128 * 256], g_duall[128 * 256];
__device__ __nv_bfloat16 g_wrTh[2 * 128 * 128], g_wrTl[2 * 128 * 128];
__device__ __nv_bfloat16 g_wlTh[2 * 128 * 128], g_wlTl[2 * 128 * 128];
__device__ __nv_bfloat16 g_fhi[32 * 128], g_flo[32 * 128];

// ---------------- helpers ----------------------------------------------------
__device__ __forceinline__ uint32_t smem_u32(const void* p) {
    return (uint32_t)__cvta_generic_to_shared(p);
}

__device__ __forceinline__ void ldsm4(uint32_t* r, uint32_t addr) {
    asm volatile("ldmatrix.sync.aligned.m8n8.x4.shared.b16 {%0,%1,%2,%3}, [%4];"
                 : "=r"(r[0]), "=r"(r[1]), "=r"(r[2]), "=r"(r[3]) : "r"(addr));
}

__device__ __forceinline__ void mma_bf16(float* c, const uint32_t* a, const uint32_t* b) {
    asm volatile(
        "mma.sync.aligned.m16n8k16.row.col.f32.bf16.bf16.f32 "
        "{%0,%1,%2,%3}, {%4,%5,%6,%7}, {%8,%9}, {%0,%1,%2,%3};"
        : "+f"(c[0]), "+f"(c[1]), "+f"(c[2]), "+f"(c[3])
        : "r"(a[0]), "r"(a[1]), "r"(a[2]), "r"(a[3]), "r"(b[0]), "r"(b[1]));
}

__device__ __forceinline__ uint32_t pack2(__nv_bfloat16 a, __nv_bfloat16 b) {
    uint32_t lo = (uint32_t)__bfloat16_as_ushort(a);
    uint32_t hi = (uint32_t)__bfloat16_as_ushort(b);
    return lo | (hi << 16);
}

__device__ __forceinline__ float2 bf2f(uint32_t u) {
    float2 r;
    r.x = __bfloat162float(__ushort_as_bfloat16((unsigned short)(u & 0xffff)));
    r.y = __bfloat162float(__ushort_as_bfloat16((unsigned short)(u >> 16)));
    return r;
}

__device__ __forceinline__ void cpa16(uint32_t dst, const void* src, int szbytes) {
    asm volatile("cp.async.cg.shared.global [%0], [%1], 16, %2;"
                 :: "r"(dst), "l"(src), "r"(szbytes));
}

__device__ __forceinline__ uint2 split_hi(float4 v) {
    __nv_bfloat16 h0 = __float2bfloat16(v.x), h1 = __float2bfloat16(v.y);
    __nv_bfloat16 h2 = __float2bfloat16(v.z), h3 = __float2bfloat16(v.w);
    return make_uint2(pack2(h0, h1), pack2(h2, h3));
}
__device__ __forceinline__ uint2 split_lo(float4 v) {
    __nv_bfloat16 h0 = __float2bfloat16(v.x), h1 = __float2bfloat16(v.y);
    __nv_bfloat16 h2 = __float2bfloat16(v.z), h3 = __float2bfloat16(v.w);
    __nv_bfloat16 l0 = __float2bfloat16(v.x - __bfloat162float(h0));
    __nv_bfloat16 l1 = __float2bfloat16(v.y - __bfloat162float(h1));
    __nv_bfloat16 l2 = __float2bfloat16(v.z - __bfloat162float(h2));
    __nv_bfloat16 l3 = __float2bfloat16(v.w - __bfloat162float(h3));
    return make_uint2(pack2(l0, l1), pack2(l2, l3));
}

// ---------------- small utility kernels ------------------------------------
__global__ void zero_kernel(int* p, int n) {
    int i = blockIdx.x * blockDim.x + threadIdx.x;
    if (i < n) p[i] = 0;
}

__global__ void hist_kernel(const int* __restrict__ dst, int* __restrict__ deg, int n) {
    for (int i = blockIdx.x * blockDim.x + threadIdx.x; i < n; i += gridDim.x * blockDim.x)
        atomicAdd(&deg[dst[i]], 1);
}

__global__ void scan_blocks(const int* __restrict__ in, int* __restrict__ out,
                            int* __restrict__ partials, int n) {
    __shared__ int sh[256];
    int t = threadIdx.x;
    int base = blockIdx.x * 1024 + t * 4;
    int v0 = (base + 0 < n) ? in[base + 0] : 0;
    int v1 = (base + 1 < n) ? in[base + 1] : 0;
    int v2 = (base + 2 < n) ? in[base + 2] : 0;
    int v3 = (base + 3 < n) ? in[base + 3] : 0;
    int s = v0 + v1 + v2 + v3;
    sh[t] = s;
    __syncthreads();
    for (int off = 1; off < 256; off <<= 1) {
        int y = (t >= off) ? sh[t - off] : 0;
        __syncthreads();
        sh[t] += y;
        __syncthreads();
    }
    int excl = sh[t] - s;
    if (t == 255) partials[blockIdx.x] = sh[255];
    int run = excl;
    if (base + 0 < n) out[base + 0] = run; run += v0;
    if (base + 1 < n) out[base + 1] = run; run += v1;
    if (base + 2 < n) out[base + 2] = run; run += v2;
    if (base + 3 < n) out[base + 3] = run;
}

__global__ void scan_partials(int* partials, int nb) {
    __shared__ int sh[256];
    int t = threadIdx.x;
    int v = (t < nb) ? partials[t] : 0;
    sh[t] = v;
    __syncthreads();
    for (int off = 1; off < 256; off <<= 1) {
        int y = (t >= off) ? sh[t - off] : 0;
        __syncthreads();
        sh[t] += y;
        __syncthreads();
    }
    if (t < nb) partials[t] = sh[t] - v;
}

__global__ void scan_add(int* __restrict__ out, const int* __restrict__ partials, int n) {
    for (int i = blockIdx.x * blockDim.x + threadIdx.x; i < n; i += gridDim.x * blockDim.x)
        out[i] += partials[i >> 10];
}

__global__ void fill_kernel(const int* __restrict__ src, const int* __restrict__ dst,
                            const int* __restrict__ rowptr, int* __restrict__ cursor,
                            int* __restrict__ col, int n) {
    for (int e = blockIdx.x * blockDim.x + threadIdx.x; e < n; e += gridDim.x * blockDim.x) {
        int d = dst[e];
        int p = rowptr[d] + atomicAdd(&cursor[d], 1);
        col[p] = src[e];
    }
}

// fp32 [N][128] -> bf16 hi/lo planes
__global__ void conv_hl(const float* __restrict__ x, __nv_bfloat16* __restrict__ hi,
                        __nv_bfloat16* __restrict__ lo, int nq) {
    int i = blockIdx.x * blockDim.x + threadIdx.x;
    if (i >= nq) return;
    float4 v = ((const float4*)x)[i];
    ((uint2*)hi)[i] = split_hi(v);
    ((uint2*)lo)[i] = split_lo(v);
}

// transposed bf16 hi/lo weight planes
__global__ void prep_weights(const float* __restrict__ Wl, const float* __restrict__ Wr,
                             const float* __restrict__ W_out,
                             __nv_bfloat16* __restrict__ dualh, __nv_bfloat16* __restrict__ duall,
                             __nv_bfloat16* __restrict__ wrTh, __nv_bfloat16* __restrict__ wrTl,
                             __nv_bfloat16* __restrict__ wlTh, __nv_bfloat16* __restrict__ wlTl,
                             __nv_bfloat16* __restrict__ fhi, __nv_bfloat16* __restrict__ flo) {
    int i = blockIdx.x * blockDim.x + threadIdx.x;
    if (i >= 102400) return;
    float v;
    __nv_bfloat16* dh;
    __nv_bfloat16* dl;
    int idx;
    if (i < 32768) {
        int n = i >> 8, k = i & 255;
        if (k < DIM) v = Wl[((size_t)1 * DIM + k) * DIM + n];
        else         v = Wr[((size_t)1 * DIM + (k - DIM)) * DIM + n];
        dh = dualh; dl = duall; idx = i;
    } else if (i < 65536) {
        int r = i - 32768;
        int g = r >> 14, rr = r & 16383;
        int n = rr >> 7, k = rr & 127;
        v = Wr[((size_t)(g * 2 + 0) * DIM + k) * DIM + n];
        dh = wrTh; dl = wrTl; idx = r;
    } else if (i < 98304) {
        int r = i - 65536;
        int g = r >> 14, rr = r & 16383;
        int n = rr >> 7, k = rr & 127;
        v = Wl[((size_t)(g * 2 + 0) * DIM + k) * DIM + n];
        dh = wlTh; dl = wlTl; idx = r;
    } else {
        int r = i - 98304;
        int n = r >> 7, k = r & 127;
        v = W_out[(size_t)k * D_OUT + n];
        dh = fhi; dl = flo; idx = r;
    }
    __nv_bfloat16 h = __float2bfloat16(v);
    dh[idx] = h;
    dl[idx] = __float2bfloat16(v - __bfloat162float(h));
}

// ---------------- mean aggregation of RAW fp32 rows -> bf16 hi/lo planes -----
__global__ void aggregate_raw(const float* __restrict__ x,
                              const int* __restrict__ rowptr,
                              const int* __restrict__ col,
                              __nv_bfloat16* __restrict__ mh,
                              __nv_bfloat16* __restrict__ ml, int ndst) {
    int warp = (blockIdx.x * blockDim.x + threadIdx.x) >> 5;
    int lane = threadIdx.x & 31;
    if (warp >= ndst) return;
    int start = rowptr[warp];
    int end   = rowptr[warp + 1];
    const float4* P = (const float4*)x;
    float a0 = 0.f, a1 = 0.f, a2 = 0.f, a3 = 0.f;
    int e = start;
    for (; e + 1 < end; e += 2) {
        int s0 = __ldg(&col[e]);
        int s1 = __ldg(&col[e + 1]);
        float4 v0 = __ldg(&P[(size_t)s0 * 32 + lane]);
        float4 v1 = __ldg(&P[(size_t)s1 * 32 + lane]);
        a0 += v0.x + v1.x; a1 += v0.y + v1.y;
        a2 += v0.z + v1.z; a3 += v0.w + v1.w;
    }
    if (e < end) {
        int s0 = __ldg(&col[e]);
        float4 v0 = __ldg(&P[(size_t)s0 * 32 + lane]);
        a0 += v0.x; a1 += v0.y; a2 += v0.z; a3 += v0.w;
    }
    int deg = end - start;
    float inv = 1.f / (float)(deg > 1 ? deg : 1);
    float4 m = make_float4(a0 * inv, a1 * inv, a2 * inv, a3 * inv);
    ((uint2*)mh)[(size_t)warp * 32 + lane] = split_hi(m);
    ((uint2*)ml)[(size_t)warp * 32 + lane] = split_lo(m);
}

// ---------------- mean aggregation, flat fp32 gather -> fp32 addend ----------
__global__ void aggregate_flat(const float* __restrict__ y,
                               const int* __restrict__ rowptr,
                               const int* __restrict__ col,
                               float* __restrict__ D, int ndst) {
    int warp = (blockIdx.x * blockDim.x + threadIdx.x) >> 5;
    int lane = threadIdx.x & 31;
    if (warp >= ndst) return;
    int start = rowptr[warp];
    int end   = rowptr[warp + 1];
    const float4* P = (const float4*)y;
    float a0 = 0.f, a1 = 0.f, a2 = 0.f, a3 = 0.f;
    int e = start;
    for (; e + 1 < end; e += 2) {
        int s0 = __ldg(&col[e]);
        int s1 = __ldg(&col[e + 1]);
        float4 v0 = __ldg(&P[(size_t)s0 * 32 + lane]);
        float4 v1 = __ldg(&P[(size_t)s1 * 32 + lane]);
        a0 += v0.x + v1.x; a1 += v0.y + v1.y;
        a2 += v0.z + v1.z; a3 += v0.w + v1.w;
    }
    if (e < end) {
        int s0 = __ldg(&col[e]);
        float4 v0 = __ldg(&P[(size_t)s0 * 32 + lane]);
        a0 += v0.x; a1 += v0.y; a2 += v0.z; a3 += v0.w;
    }
    int deg = end - start;
    float inv = 1.f / (float)(deg > 1 ? deg : 1);
    ((float4*)D)[(size_t)warp * 32 + lane] = make_float4(a0 * inv, a1 * inv,
                                                         a2 * inv, a3 * inv);
}

// ---------------- mma.sync bf16 GEMM, 3-pass hi/lo, cp.async 2-stage ---------
// AD: optional fp32 [M][128] addend. FUSE: second GEMM @ FW[32][128].
// AF32: A supplied as raw fp32 [M][128] (Af32); in-kernel hi/lo split.
template <int BN, int WROWS, int KTOT, bool DUAL, bool ACT, bool WHL, bool FUSE, bool AF32>
__global__ __launch_bounds__(256) void mma_gemm(
    const __nv_bfloat16* __restrict__ Ah0, const __nv_bfloat16* __restrict__ Al0,
    const __nv_bfloat16* __restrict__ Ah1, const __nv_bfloat16* __restrict__ Al1,
    const float* __restrict__ Af32,
    const __nv_bfloat16* __restrict__ Bh, const __nv_bfloat16* __restrict__ Bl,
    const float* __restrict__ bias0, const float* __restrict__ bias1,
    const float* __restrict__ AD,
    float* __restrict__ C, __nv_bfloat16* __restrict__ OutH,
    __nv_bfloat16* __restrict__ OutL,
    const __nv_bfloat16* __restrict__ FWh, const __nv_bfloat16* __restrict__ FWl,
    const float* __restrict__ bout, int M)
{
    constexpr int WCOLS  = 8 / WROWS;
    constexpr int WARP_M = 128 / WROWS;
    constexpr int WARP_N = BN / WCOLS;
    constexpr int TM = WARP_M / 16;
    constexpr int TN = WARP_N / 8;
    constexpr int AS = 40;
    constexpr int A_PLANE = 128 * AS * 2;
    constexpr int B_PLANE = BN * AS * 2;
    constexpr int STAGE = 2 * A_PLANE + 2 * B_PLANE;
    constexpr int NK = KTOT / 32;
    constexpr int PC = 68;

    extern __shared__ char dynsmem[];
    __shared__ float s_bias[BN];

    const int tid  = threadIdx.x;
    const int wid  = tid >> 5;
    const int lane = tid & 31;
    const int wrow = wid / WCOLS;
    const int wcol = wid % WCOLS;
    const int rowbase = blockIdx.x * 128;
    const uint32_t sb = smem_u32(dynsmem);
    const uint32_t scr = sb + 2 * STAGE;          // fp32 A scratch (AF32 only)
    float* scrp = (float*)(dynsmem + 2 * STAGE);

    if (tid < BN) s_bias[tid] = bias0[tid] + (bias1 ? bias1[tid] : 0.f);

    float acc[TM][TN][4];
#pragma unroll
    for (int i = 0; i < TM; i++)
#pragma unroll
        for (int j = 0; j < TN; j++)
#pragma unroll
            for (int q = 0; q < 4; q++) acc[i][j][q] = 0.f;

    uint32_t aoff[TM][2];
#pragma unroll
    for (int i = 0; i < TM; i++)
#pragma unroll
        for (int ks = 0; ks < 2; ks++) {
            int row = wrow * WARP_M + i * 16 + (lane & 15);
            int colk = ks * 16 + (lane >> 4) * 8;
            aoff[i][ks] = (uint32_t)(row * AS + colk) * 2;
        }
    uint32_t boff[TN / 2][2];
#pragma unroll
    for (int jj = 0; jj < TN / 2; jj++)
#pragma unroll
        for (int ks = 0; ks < 2; ks++) {
            int n = wcol * WARP_N + jj * 16 + (lane & 7) + ((lane >> 4) & 1) * 8;
            int k = ks * 16 + ((lane >> 3) & 1) * 8;
            boff[jj][ks] = (uint32_t)(n * AS + k) * 2;
        }

    auto load_B = [&](int s, int k0) {
        uint32_t su = sb + (uint32_t)s * STAGE + 2 * A_PLANE;
#pragma unroll
        for (int idx = tid; idx < BN * 4; idx += 256) {
            int n = idx >> 2, q = idx & 3;
            uint32_t d = su + (uint32_t)(n * AS + q * 8) * 2;
            cpa16(d, Bh + (size_t)n * KTOT + k0 + q * 8, 16);
            cpa16(d + B_PLANE, Bl + (size_t)n * KTOT + k0 + q * 8, 16);
        }
    };

    auto load_A_planes = [&](int s, int k0) {
        uint32_t su = sb + (uint32_t)s * STAGE;
        const __nv_bfloat16* A_h = Ah0;
        const __nv_bfloat16* A_l = Al0;
        int ka = k0;
        if (DUAL && k0 >= DIM) { A_h = Ah1; A_l = Al1; ka = k0 - DIM; }
#pragma unroll
        for (int idx = tid; idx < 512; idx += 256) {
            int r = idx >> 2, q = idx & 3;
            int row = rowbase + r;
            int sz = (row < M) ? 16 : 0;
            int crow = row < M ? row : (M - 1);
            uint32_t d = su + (uint32_t)(r * AS + q * 8) * 2;
            cpa16(d, A_h + (size_t)crow * DIM + ka + q * 8, sz);
            cpa16(d + A_PLANE, A_l + (size_t)crow * DIM + ka + q * 8, sz);
        }
    };

    auto load_A_f32 = [&](int k0) {   // cp.async fp32 A chunk into scratch
#pragma unroll
        for (int p = 0; p < 4; p++) {
            int idx = p * 256 + tid;
            int r = idx >> 3, q = idx & 7;
            int row = rowbase + r;
            int sz = (row < M) ? 16 : 0;
            int crow = row < M ? row : (M - 1);
            cpa16(scr + (uint32_t)(r * 32 + q * 4) * 4,
                  Af32 + (size_t)crow * DIM + k0 + q * 4, sz);
        }
    };

    auto do_mma = [&](int s) {
        uint32_t su = sb + (uint32_t)s * STAGE;
        const uint32_t uAh = su;
        const uint32_t uAl = su + A_PLANE;
        const uint32_t uBh = su + 2 * A_PLANE;
        const uint32_t uBl = uBh + B_PLANE;
#pragma unroll
        for (int ks = 0; ks < 2; ks++) {
            uint32_t ah[TM][4], al[TM][4];
#pragma unroll
            for (int i = 0; i < TM; i++) {
                ldsm4(ah[i], uAh + aoff[i][ks]);
                ldsm4(al[i], uAl + aoff[i][ks]);
            }
            uint32_t bh[TN][2], bl_[TN][2];
#pragma unroll
            for (int jj = 0; jj < TN / 2; jj++) {
                uint32_t r4[4];
                ldsm4(r4, uBh + boff[jj][ks]);
                bh[2 * jj][0] = r4[0]; bh[2 * jj][1] = r4[1];
                bh[2 * jj + 1][0] = r4[2]; bh[2 * jj + 1][1] = r4[3];
                ldsm4(r4, uBl + boff[jj][ks]);
                bl_[2 * jj][0] = r4[0]; bl_[2 * jj][1] = r4[1];
                bl_[2 * jj + 1][0] = r4[2]; bl_[2 * jj + 1][1] = r4[3];
            }
#pragma unroll
            for (int i = 0; i < TM; i++)
#pragma unroll
                for (int j = 0; j < TN; j++) {
                    mma_bf16(acc[i][j], ah[i], bh[j]);
                    mma_bf16(acc[i][j], ah[i], bl_[j]);
                    mma_bf16(acc[i][j], al[i], bh[j]);
                }
        }
    };

    if (!AF32) {
        load_A_planes(0, 0);
        load_B(0, 0);
        asm volatile("cp.async.commit_group;");
        for (int c = 0; c < NK; c++) {
            if (c + 1 < NK) {
                load_A_planes((c + 1) & 1, (c + 1) * 32);
                load_B((c + 1) & 1, (c + 1) * 32);
                asm volatile("cp.async.commit_group;");
                asm volatile("cp.async.wait_group 1;");
            } else {
                asm volatile("cp.async.wait_group 0;");
            }
            __syncthreads();
            do_mma(c & 1);
            __syncthreads();
        }
    } else {
        load_A_f32(0);
        load_B(0, 0);
        asm volatile("cp.async.commit_group;");
        for (int c = 0; c < NK; c++) {
            asm volatile("cp.async.wait_group 0;");
            __syncthreads();
            // convert fp32 scratch -> bf16 hi/lo planes of stage c&1
            {
                uint32_t su = sb + (uint32_t)(c & 1) * STAGE;
                char* ph = dynsmem + ((size_t)(c & 1) * STAGE);
#pragma unroll
                for (int p = 0; p < 4; p++) {
                    int idx = p * 256 + tid;
                    int r = idx >> 3, q = idx & 7;
                    float4 v = *(float4*)(scrp + r * 32 + q * 4);
                    *(uint2*)(ph + (uint32_t)(r * AS + q * 4) * 2) = split_hi(v);
                    *(uint2*)(ph + A_PLANE + (uint32_t)(r * AS + q * 4) * 2) = split_lo(v);
                }
                (void)su;
            }
            __syncthreads();
            if (c + 1 < NK) {
                load_A_f32((c + 1) * 32);
                load_B((c + 1) & 1, (c + 1) * 32);
                asm volatile("cp.async.commit_group;");
            }
            do_mma(c & 1);
            __syncthreads();
        }
    }

    if (!FUSE) {
#pragma unroll
        for (int i = 0; i < TM; i++) {
#pragma unroll
            for (int j = 0; j < TN; j++) {
                int row0 = rowbase + wrow * WARP_M + i * 16 + (lane >> 2);
                int colb = wcol * WARP_N + j * 8 + (lane & 3) * 2;
                float b0 = s_bias[colb], b1 = s_bias[colb + 1];
#pragma unroll
                for (int h = 0; h < 2; h++) {
                    int row = row0 + h * 8;
                    if (row < M) {
                        float dx = 0.f, dy = 0.f;
                        if (AD) {
                            float2 dv = *(const float2*)&AD[(size_t)row * DIM + colb];
                            dx = dv.x; dy = dv.y;
                        }
                        float vx = acc[i][j][2 * h + 0] + b0 + dx;
                        float vy = acc[i][j][2 * h + 1] + b1 + dy;
                        if (ACT) {
                            vx = vx > 0.f ? vx : 0.01f * vx;
                            vy = vy > 0.f ? vy : 0.01f * vy;
                        }
                        if (WHL) {
                            __nv_bfloat16 hx = __float2bfloat16(vx);
                            __nv_bfloat16 hy = __float2bfloat16(vy);
                            __nv_bfloat16 lx = __float2bfloat16(vx - __bfloat162float(hx));
                            __nv_bfloat16 ly = __float2bfloat16(vy - __bfloat162float(hy));
                            *(uint32_t*)&OutH[(size_t)row * BN + colb] = pack2(hx, hy);
                            *(uint32_t*)&OutL[(size_t)row * BN + colb] = pack2(lx, ly);
                        } else {
                            *(float2*)&C[(size_t)row * BN + colb] = make_float2(vx, vy);
                        }
                    }
                }
            }
        }
    } else {
        // ---- fused output projection: act-tile (smem, bf16 hi/lo pairs) @ Wout
        uint32_t* sC_hi = (uint32_t*)dynsmem;          // [128][PC]
        uint32_t* sC_lo = sC_hi + 128 * PC;
        uint32_t* sW_hi = sC_lo + 128 * PC;            // [32][PC]
        uint32_t* sW_lo = sW_hi + 32 * PC;

        for (int idx = tid; idx < 32 * 64; idx += 256) {
            int n = idx >> 6, kp = idx & 63;
            sW_hi[n * PC + kp] = ((const uint32_t*)FWh)[n * 64 + kp];
            sW_lo[n * PC + kp] = ((const uint32_t*)FWl)[n * 64 + kp];
        }
#pragma unroll
        for (int i = 0; i < TM; i++) {
#pragma unroll
            for (int j = 0; j < TN; j++) {
                int lrow0 = wrow * WARP_M + i * 16 + (lane >> 2);
                int colb = wcol * WARP_N + j * 8 + (lane & 3) * 2;
                int pair = colb >> 1;
                float b0 = s_bias[colb], b1 = s_bias[colb + 1];
#pragma unroll
                for (int h = 0; h < 2; h++) {
                    int lrow = lrow0 + h * 8;
                    int grow = rowbase + lrow;
                    float dx = 0.f, dy = 0.f;
                    if (AD && grow < M) {
                        float2 dv = *(const float2*)&AD[(size_t)grow * DIM + colb];
                        dx = dv.x; dy = dv.y;
                    }
                    float vx = acc[i][j][2 * h + 0] + b0 + dx;
                    float vy = acc[i][j][2 * h + 1] + b1 + dy;
                    vx = vx > 0.f ? vx : 0.01f * vx;
                    vy = vy > 0.f ? vy : 0.01f * vy;
                    __nv_bfloat16 hx = __float2bfloat16(vx);
                    __nv_bfloat16 hy = __float2bfloat16(vy);
                    __nv_bfloat16 lx = __float2bfloat16(vx - __bfloat162float(hx));
                    __nv_bfloat16 ly = __float2bfloat16(vy - __bfloat162float(hy));
                    sC_hi[lrow * PC + pair] = pack2(hx, hy);
                    sC_lo[lrow * PC + pair] = pack2(lx, ly);
                }
            }
        }
        __syncthreads();

        const int g = lane >> 2, tig = lane & 3;
        const int w2row = wid * 16;
        float acc2[4][4];
#pragma unroll
        for (int j = 0; j < 4; j++)
#pragma unroll
            for (int q = 0; q < 4; q++) acc2[j][q] = 0.f;

#pragma unroll
        for (int ks = 0; ks < 8; ks++) {
            int ro  = (w2row + g) * PC + ks * 8 + tig;
            int ro8 = ro + 8 * PC;
            uint32_t ah[4] = {sC_hi[ro], sC_hi[ro8], sC_hi[ro + 4], sC_hi[ro8 + 4]};
            uint32_t al[4] = {sC_lo[ro], sC_lo[ro8], sC_lo[ro + 4], sC_lo[ro8 + 4]};
#pragma unroll
            for (int j = 0; j < 4; j++) {
                int bo = (j * 8 + g) * PC + ks * 8 + tig;
                uint32_t bh[2]  = {sW_hi[bo], sW_hi[bo + 4]};
                uint32_t bl2[2] = {sW_lo[bo], sW_lo[bo + 4]};
                mma_bf16(acc2[j], ah, bh);
                mma_bf16(acc2[j], ah, bl2);
                mma_bf16(acc2[j], al, bh);
            }
        }
#pragma unroll
        for (int j = 0; j < 4; j++) {
            int colo = j * 8 + tig * 2;
            float bo0 = bout[colo], bo1 = bout[colo + 1];
            int r0 = rowbase + w2row + g;
            if (r0 < M)
                *(float2*)&C[(size_t)r0 * D_OUT + colo] =
                    make_float2(acc2[j][0] + bo0, acc2[j][1] + bo1);
            int r1 = r0 + 8;
            if (r1 < M)
                *(float2*)&C[(size_t)r1 * D_OUT + colo] =
                    make_float2(acc2[j][2] + bo0, acc2[j][3] + bo1);
        }
    }
}

// ---------------- host side -------------------------------------------------
static void build_csr(const int* src, const int* dst, int ndst,
                      int* rowptr, int* col, int* deg, int* parts, cudaStream_t st) {
    int n1 = ndst + 1;
    zero_kernel<<<(n1 + 255) / 256, 256, 0, st>>>(deg, n1);
    hist_kernel<<<2048, 256, 0, st>>>(dst, deg, NEDGE);
    int nb = (n1 + 1023) / 1024;
    scan_blocks<<<nb, 256, 0, st>>>(deg, rowptr, parts, n1);
    scan_partials<<<1, 256, 0, st>>>(parts, nb);
    scan_add<<<nb, 256, 0, st>>>(rowptr, parts, n1);
    zero_kernel<<<(n1 + 255) / 256, 256, 0, st>>>(deg, n1);
    fill_kernel<<<2048, 256, 0, st>>>(src, dst, rowptr, deg, col, NEDGE);
}

extern "C" void kernel_launch(void* const* d_in, const int* in_sizes, int n_in,
                              void* d_out, int out_size) {
    (void)in_sizes; (void)n_in; (void)out_size;
    const float* x_host  = (const float*)d_in[0];
    const float* x_flow  = (const float*)d_in[1];
    const int*   ehf_src = (const int*)d_in[2];
    const int*   ehf_dst = (const int*)d_in[3];
    const int*   efh_src = (const int*)d_in[4];
    const int*   efh_dst = (const int*)d_in[5];
    const float* Wl      = (const float*)d_in[6];
    const float* bl      = (const float*)d_in[7];
    const float* Wr      = (const float*)d_in[8];
    const float* br      = (const float*)d_in[9];
    const float* W_out   = (const float*)d_in[10];
    const float* b_out   = (const float*)d_in[11];
    float* out = (float*)d_out;

    static bool inited = false;
    static cudaStream_t s1, s2, s3;
    static cudaEvent_t evFork, evPH, evCsrF, evCsrH, evS1done;
    if (!inited) {
        cudaStreamCreateWithFlags(&s1, cudaStreamNonBlocking);
        cudaStreamCreateWithFlags(&s2, cudaStreamNonBlocking);
        cudaStreamCreateWithFlags(&s3, cudaStreamNonBlocking);
        cudaEventCreateWithFlags(&evFork,   cudaEventDisableTiming);
        cudaEventCreateWithFlags(&evPH,     cudaEventDisableTiming);
        cudaEventCreateWithFlags(&evCsrF,   cudaEventDisableTiming);
        cudaEventCreateWithFlags(&evCsrH,   cudaEventDisableTiming);
        cudaEventCreateWithFlags(&evS1done, cudaEventDisableTiming);
        inited = true;
    }

    int *deg, *degh, *rpf, *rph, *colf, *colh, *parts, *partsh;
    float *zerob, *D1, *D2, *y0, *y2;
    __nv_bfloat16 *xhh, *xhl, *faH, *faL, *haH, *haL, *mhH, *mhL;
    __nv_bfloat16 *dualh, *duall, *wrTh, *wrTl, *wlTh, *wlTl, *fhi, *flo;
    cudaGetSymbolAddress((void**)&deg,    g_deg);
    cudaGetSymbolAddress((void**)&degh,   g_deg_h);
    cudaGetSymbolAddress((void**)&rpf,    g_rowptr_f);
    cudaGetSymbolAddress((void**)&rph,    g_rowptr_h);
    cudaGetSymbolAddress((void**)&colf,   g_col_f);
    cudaGetSymbolAddress((void**)&colh,   g_col_h);
    cudaGetSymbolAddress((void**)&parts,  g_partials);
    cudaGetSymbolAddress((void**)&partsh, g_partials_h);
    cudaGetSymbolAddress((void**)&zerob,  g_zero);
    cudaGetSymbolAddress((void**)&D1,     g_D1);
    cudaGetSymbolAddress((void**)&D2,     g_D2);
    cudaGetSymbolAddress((void**)&y0,     g_y0);
    cudaGetSymbolAddress((void**)&y2,     g_y2);
    cudaGetSymbolAddress((void**)&xhh, g_xhh); cudaGetSymbolAddress((void**)&xhl, g_xhl);
    cudaGetSymbolAddress((void**)&faH, g_faH); cudaGetSymbolAddress((void**)&faL, g_faL);
    cudaGetSymbolAddress((void**)&haH, g_haH); cudaGetSymbolAddress((void**)&haL, g_haL);
    cudaGetSymbolAddress((void**)&mhH, g_mhH); cudaGetSymbolAddress((void**)&mhL, g_mhL);
    cudaGetSymbolAddress((void**)&dualh, g_dualh); cudaGetSymbolAddress((void**)&duall, g_duall);
    cudaGetSymbolAddress((void**)&wrTh, g_wrTh); cudaGetSymbolAddress((void**)&wrTl, g_wrTl);
    cudaGetSymbolAddress((void**)&wlTh, g_wlTh); cudaGetSymbolAddress((void**)&wlTl, g_wlTl);
    cudaGetSymbolAddress((void**)&fhi, g_fhi); cudaGetSymbolAddress((void**)&flo, g_flo);

    const int SMEM_MAIN   = 81920;   // 2-stage mainloop
    const int SMEM_AF32   = 98304;   // + 16KB fp32 A scratch
    const int SMEM_FUSE32 = 87040;   // FUSE (Wout projection)
    cudaFuncSetAttribute(mma_gemm<128, 2, 128, false, false, false, false, false>,
                         cudaFuncAttributeMaxDynamicSharedMemorySize, SMEM_MAIN);
    cudaFuncSetAttribute(mma_gemm<128, 2, 128, false, true, true, false, true>,
                         cudaFuncAttributeMaxDynamicSharedMemorySize, SMEM_AF32);
    cudaFuncSetAttribute(mma_gemm<128, 2, 256, true, true, true, false, false>,
                         cudaFuncAttributeMaxDynamicSharedMemorySize, SMEM_MAIN);
    cudaFuncSetAttribute(mma_gemm<128, 2, 128, false, true, false, true, false>,
                         cudaFuncAttributeMaxDynamicSharedMemorySize, SMEM_FUSE32);

    const float* bl0 = bl + 0 * DIM;  const float* br0 = br + 0 * DIM;  // l0 flow
    const float* bl1 = bl + 1 * DIM;  const float* br1 = br + 1 * DIM;  // l0 host
    const float* bl2 = bl + 2 * DIM;  const float* br2 = br + 2 * DIM;  // l1 flow

    // ---- fork: all side streams branch from one recorded event --------------
    cudaEventRecord(evFork, 0);
    cudaStreamWaitEvent(s1, evFork, 0);
    cudaStreamWaitEvent(s2, evFork, 0);
    cudaStreamWaitEvent(s3, evFork, 0);

    // ---- s2: flow CSR [evCsrF] ----------------------------------------------
    build_csr(ehf_src, ehf_dst, N_FLOWN, rpf, colf, deg, parts, s2);
    cudaEventRecord(evCsrF, s2);

    // ---- s3: host CSR [evCsrH] ----------------------------------------------
    build_csr(efh_src, efh_dst, N_HOSTN, rph, colh, degh, partsh, s3);
    cudaEventRecord(evCsrH, s3);

    // ---- s0 head: prep + conv(x_host) [evPH], premul y0 (fp32) --------------
    prep_weights<<<(102400 + 255) / 256, 256>>>(
        Wl, Wr, W_out, dualh, duall, wrTh, wrTl, wlTh, wlTl, fhi, flo);
    conv_hl<<<(N_HOSTN * 32 + 255) / 256, 256>>>(x_host, xhh, xhl, N_HOSTN * 32);
    cudaEventRecord(evPH, 0);
    mma_gemm<128, 2, 128, false, false, false, false, false>
        <<<(N_HOSTN + 127) / 128, 256, SMEM_MAIN>>>(
        xhh, xhl, nullptr, nullptr, nullptr, wlTh, wlTl, zerob, nullptr, nullptr,
        y0, nullptr, nullptr, nullptr, nullptr, nullptr, N_HOSTN);

    // ---- s1: agg_h from RAW x_flow; gemm_h1; y2 premul; agg_f2 --------------
    cudaStreamWaitEvent(s1, evCsrH, 0);
    aggregate_raw<<<(N_HOSTN + 7) / 8, 256, 0, s1>>>(x_flow, rph, colh, mhH, mhL, N_HOSTN);
    cudaStreamWaitEvent(s1, evPH, 0);
    mma_gemm<128, 2, 256, true, true, true, false, false>
        <<<(N_HOSTN + 127) / 128, 256, SMEM_MAIN, s1>>>(
        mhH, mhL, xhh, xhl, nullptr, dualh, duall, bl1, br1, nullptr,
        nullptr, haH, haL, nullptr, nullptr, nullptr, N_HOSTN);
    mma_gemm<128, 2, 128, false, false, false, false, false>
        <<<(N_HOSTN + 127) / 128, 256, SMEM_MAIN, s1>>>(
        haH, haL, nullptr, nullptr, nullptr, wlTh + 128 * 128, wlTl + 128 * 128,
        zerob, nullptr, nullptr, y2, nullptr, nullptr, nullptr, nullptr, nullptr, N_HOSTN);
    cudaStreamWaitEvent(s1, evCsrF, 0);
    aggregate_flat<<<(N_FLOWN + 7) / 8, 256, 0, s1>>>(y2, rpf, colf, D2, N_FLOWN);
    cudaEventRecord(evS1done, s1);

    // ---- s0 tail: agg_f1 (flat on y0), flow layer-1 GEMM (raw fp32 A) -------
    cudaStreamWaitEvent(0, evCsrF, 0);
    aggregate_flat<<<(N_FLOWN + 7) / 8, 256>>>(y0, rpf, colf, D1, N_FLOWN);
    mma_gemm<128, 2, 128, false, true, true, false, true>
        <<<(N_FLOWN + 127) / 128, 256, SMEM_AF32>>>(
        nullptr, nullptr, nullptr, nullptr, x_flow, wrTh, wrTl, bl0, br0, D1,
        nullptr, faH, faL, nullptr, nullptr, nullptr, N_FLOWN);

    // ---- join: fused layer-2 flow GEMM (K=128 + addend) + output projection -
    cudaStreamWaitEvent(0, evS1done, 0);
    mma_gemm<128, 2, 128, false, true, false, true, false>
        <<<(N_FLOWN + 127) / 128, 256, SMEM_FUSE32>>>(
        faH, faL, nullptr, nullptr, nullptr, wrTh + 128 * 128, wrTl + 128 * 128,
        bl2, br2, D2, out, nullptr, nullptr, fhi, flo, b_out, N_FLOWN);
}